// round 8
// baseline (speedup 1.0000x reference)
#include <cuda_runtime.h>
#include <cuda_bf16.h>
#include <cooperative_groups.h>
#include <stdint.h>

namespace cg = cooperative_groups;

// Problem dims
#define NB 32
#define NS 1024
#define NC 12
#define NE 256
#define NH 512
#define NT 50
#define NTOK (NB*NS)          // 32768

// ---------------- device scratch (allocation-free) ----------------
__device__ float g_WcihT[NE * 4 * NE];            // [k=256][1024] col 4u+g <- row g*256+u
__device__ float g_WchhT[NE * 4 * NE];
__device__ float g_bcp[4 * NE];
__device__ float g_WwihT[2 * NE * 4 * NH];        // [k=512][2048]
__device__ float g_WwhhT[NH * 4 * NH];            // [k=512][2048]
__device__ float g_bwp[4 * NH];

__device__ float g_HcA[NTOK * NE];                // char h ping
__device__ float g_HcB[NTOK * NE];                // char h pong (holds final char_feat)
__device__ float g_Cc [NTOK * NE];                // char c state
__device__ float g_XW [(size_t)NTOK * 4 * NH];    // word-input preacts + bias, [n][2048]
__device__ float g_Hsave[(size_t)NTOK * NH];      // word hidden trace [n][512]
__device__ float g_Cw [NB * NH];                  // word c state (fallback path only)

// ---------------- math helpers ----------------
__device__ __forceinline__ float sigm_(float x) {
    return __fdividef(1.f, 1.f + __expf(-x));
}
__device__ __forceinline__ float tanh_(float x) {
    return __fdividef(2.f, 1.f + __expf(-2.f * x)) - 1.f;
}

// ---------------- packed f32x2 helpers (sm_100+) ----------------
__device__ __forceinline__ unsigned long long splat2(float x) {
    unsigned long long r;
    asm("mov.b64 %0, {%1, %1};" : "=l"(r) : "f"(x));
    return r;
}
__device__ __forceinline__ void ffma2(unsigned long long& d,
                                      unsigned long long a, unsigned long long b) {
    asm("fma.rn.f32x2 %0, %1, %2, %0;" : "+l"(d) : "l"(a), "l"(b));
}
__device__ __forceinline__ float2 unpack2(unsigned long long v) {
    float2 f;
    asm("mov.b64 {%0, %1}, %2;" : "=f"(f.x), "=f"(f.y) : "l"(v));
    return f;
}

// ---------------- prep: permute/transpose weights ----------------
__global__ void prep_all_kernel(const float* __restrict__ Wc_ih,
                                const float* __restrict__ Wc_hh,
                                const float* __restrict__ bc,
                                const float* __restrict__ Ww_ih,
                                const float* __restrict__ Ww_hh,
                                const float* __restrict__ bw)
{
    const int stride = gridDim.x * blockDim.x;
    for (int idx = blockIdx.x * blockDim.x + threadIdx.x; idx < 1048576; idx += stride) {
        // word weights: [k=512][c=2048], WT[k*2048 + (4u+g)] = W[(g*512+u)*Kdim + k]
        {
            int c = idx & 2047, k = idx >> 11;      // k in [0,512)
            int u = c >> 2, g = c & 3;
            g_WwihT[idx] = Ww_ih[(g * NH + u) * (2 * NE) + k];
            g_WwhhT[idx] = Ww_hh[(g * NH + u) * NH + k];
        }
        // char weights: [k=256][c=1024]
        if (idx < 262144) {
            int c = idx & 1023, k = idx >> 10;      // k in [0,256)
            int u = c >> 2, g = c & 3;
            g_WcihT[idx] = Wc_ih[(g * NE + u) * NE + k];
            g_WchhT[idx] = Wc_hh[(g * NE + u) * NE + k];
        }
        if (idx < 2048) {
            int u = idx >> 2, g = idx & 3;
            g_bwp[idx] = bw[g * NH + u];
        }
        if (idx < 1024) {
            int u = idx >> 2, g = idx & 3;
            g_bcp[idx] = bc[g * NE + u];
        }
    }
}

// ---------------- char LSTM step (FFMA2 inner loop) ----------------
// CTA: 64 tokens x 256 gate-cols (64 units). 256 threads: tx=unit(64), ty=tokgrp(4).
// Thread micro-tile: 16 tokens (8 row-pairs) x 4 gate cols -> fused pointwise.
__global__ __launch_bounds__(256, 2)
void char_step_kernel(const int* __restrict__ char_idx,
                      const float* __restrict__ char_emb, int t)
{
    __shared__ float Xs[16][68];     // [k][token], padded
    __shared__ float Ws[16][260];    // [k][col],   padded
    __shared__ int   idxs[64];

    const int tid = threadIdx.x;
    const int tx = tid & 63;
    const int ty = tid >> 6;
    const int tok0 = blockIdx.x * 64;
    const int c0 = blockIdx.y * 256;

    float* hnew        = (t & 1) ? g_HcB : g_HcA;
    const float* hprev = (t & 1) ? g_HcA : g_HcB;

    unsigned long long acc2[8][4];   // [row-pair][col], packed f32x2
#pragma unroll
    for (int rp = 0; rp < 8; rp++) {
        acc2[rp][0] = 0ull; acc2[rp][1] = 0ull; acc2[rp][2] = 0ull; acc2[rp][3] = 0ull;
    }

    if (tid < 64) idxs[tid] = char_idx[(tok0 + tid) * NC + t];
    __syncthreads();

    const int npass = (t == 0) ? 1 : 2;
    for (int pass = 0; pass < npass; pass++) {
        const float* W = pass ? g_WchhT : g_WcihT;
        for (int kc = 0; kc < 16; kc++) {
            const int k0 = kc * 16;
            // load Xs[k][tok] (transposed): thread loads float4 along k for one token
            {
                int tok = tid >> 2, kq = tid & 3;
                float4 v;
                if (pass == 0)
                    v = *(const float4*)&char_emb[idxs[tok] * NE + k0 + kq * 4];
                else
                    v = *(const float4*)&hprev[(tok0 + tok) * NE + k0 + kq * 4];
                Xs[kq * 4 + 0][tok] = v.x;
                Xs[kq * 4 + 1][tok] = v.y;
                Xs[kq * 4 + 2][tok] = v.z;
                Xs[kq * 4 + 3][tok] = v.w;
            }
            // load Ws[k][c]: 16x256 = 1024 float4, 4 per thread
#pragma unroll
            for (int j = 0; j < 4; j++) {
                int f = tid + j * 256;
                int kk = f >> 6, cq = f & 63;
                *(float4*)&Ws[kk][cq * 4] =
                    *(const float4*)&W[(k0 + kk) * 1024 + c0 + cq * 4];
            }
            __syncthreads();
#pragma unroll
            for (int k = 0; k < 16; k++) {
                float4 b = *(float4*)&Ws[k][tx * 4];
                unsigned long long bs0 = splat2(b.x);
                unsigned long long bs1 = splat2(b.y);
                unsigned long long bs2 = splat2(b.z);
                unsigned long long bs3 = splat2(b.w);
                ulonglong2 A0 = *(const ulonglong2*)&Xs[k][ty * 16 + 0];
                ulonglong2 A1 = *(const ulonglong2*)&Xs[k][ty * 16 + 4];
                ulonglong2 A2 = *(const ulonglong2*)&Xs[k][ty * 16 + 8];
                ulonglong2 A3 = *(const ulonglong2*)&Xs[k][ty * 16 + 12];
                unsigned long long ap[8] = {A0.x, A0.y, A1.x, A1.y, A2.x, A2.y, A3.x, A3.y};
#pragma unroll
                for (int rp = 0; rp < 8; rp++) {
                    ffma2(acc2[rp][0], ap[rp], bs0);
                    ffma2(acc2[rp][1], ap[rp], bs1);
                    ffma2(acc2[rp][2], ap[rp], bs2);
                    ffma2(acc2[rp][3], ap[rp], bs3);
                }
            }
            __syncthreads();
        }
    }

    // fused LSTM pointwise epilogue
    const int u = (c0 >> 2) + tx;                  // global unit 0..255
    float4 bias = *(const float4*)&g_bcp[c0 + tx * 4];
#pragma unroll
    for (int rp = 0; rp < 8; rp++) {
        float2 gi2 = unpack2(acc2[rp][0]);
        float2 gf2 = unpack2(acc2[rp][1]);
        float2 gg2 = unpack2(acc2[rp][2]);
        float2 go2 = unpack2(acc2[rp][3]);
#pragma unroll
        for (int hh = 0; hh < 2; hh++) {
            int tok = tok0 + ty * 16 + rp * 2 + hh;
            float gi = (hh ? gi2.y : gi2.x) + bias.x;
            float gf = (hh ? gf2.y : gf2.x) + bias.y;
            float gg = (hh ? gg2.y : gg2.x) + bias.z;
            float go = (hh ? go2.y : go2.x) + bias.w;
            float cp = (t == 0) ? 0.f : g_Cc[tok * NE + u];
            float cn = sigm_(gf) * cp + sigm_(gi) * tanh_(gg);
            float h  = sigm_(go) * tanh_(cn);
            g_Cc[tok * NE + u] = cn;
            hnew[tok * NE + u] = h;
        }
    }
}

// ---------------- word-input GEMM: XW = [we ; char_feat] @ WwihT + bw (FFMA2) -------
__global__ __launch_bounds__(256, 2)
void xw_kernel(const int* __restrict__ word_idx, const float* __restrict__ word_emb)
{
    __shared__ float Xs[16][68];
    __shared__ float Ws[16][260];
    __shared__ int   idxs[64];

    const int tid = threadIdx.x;
    const int tx = tid & 63;
    const int ty = tid >> 6;
    const int tok0 = blockIdx.x * 64;
    const int c0 = blockIdx.y * 256;

    unsigned long long acc2[8][4];
#pragma unroll
    for (int rp = 0; rp < 8; rp++) {
        acc2[rp][0] = 0ull; acc2[rp][1] = 0ull; acc2[rp][2] = 0ull; acc2[rp][3] = 0ull;
    }

    if (tid < 64) idxs[tid] = word_idx[tok0 + tid];
    __syncthreads();

    for (int kc = 0; kc < 32; kc++) {
        const int k0 = kc * 16;
        {
            int tok = tid >> 2, kq = tid & 3;
            float4 v;
            if (kc < 16)
                v = *(const float4*)&word_emb[(size_t)idxs[tok] * NE + k0 + kq * 4];
            else
                v = *(const float4*)&g_HcB[(tok0 + tok) * NE + (k0 - NE) + kq * 4];
            Xs[kq * 4 + 0][tok] = v.x;
            Xs[kq * 4 + 1][tok] = v.y;
            Xs[kq * 4 + 2][tok] = v.z;
            Xs[kq * 4 + 3][tok] = v.w;
        }
#pragma unroll
        for (int j = 0; j < 4; j++) {
            int f = tid + j * 256;
            int kk = f >> 6, cq = f & 63;
            *(float4*)&Ws[kk][cq * 4] =
                *(const float4*)&g_WwihT[(k0 + kk) * 2048 + c0 + cq * 4];
        }
        __syncthreads();
#pragma unroll
        for (int k = 0; k < 16; k++) {
            float4 b = *(float4*)&Ws[k][tx * 4];
            unsigned long long bs0 = splat2(b.x);
            unsigned long long bs1 = splat2(b.y);
            unsigned long long bs2 = splat2(b.z);
            unsigned long long bs3 = splat2(b.w);
            ulonglong2 A0 = *(const ulonglong2*)&Xs[k][ty * 16 + 0];
            ulonglong2 A1 = *(const ulonglong2*)&Xs[k][ty * 16 + 4];
            ulonglong2 A2 = *(const ulonglong2*)&Xs[k][ty * 16 + 8];
            ulonglong2 A3 = *(const ulonglong2*)&Xs[k][ty * 16 + 12];
            unsigned long long ap[8] = {A0.x, A0.y, A1.x, A1.y, A2.x, A2.y, A3.x, A3.y};
#pragma unroll
            for (int rp = 0; rp < 8; rp++) {
                ffma2(acc2[rp][0], ap[rp], bs0);
                ffma2(acc2[rp][1], ap[rp], bs1);
                ffma2(acc2[rp][2], ap[rp], bs2);
                ffma2(acc2[rp][3], ap[rp], bs3);
            }
        }
        __syncthreads();
    }

    float4 bias = *(const float4*)&g_bwp[c0 + tx * 4];
#pragma unroll
    for (int rp = 0; rp < 8; rp++) {
        float2 o0 = unpack2(acc2[rp][0]);
        float2 o1 = unpack2(acc2[rp][1]);
        float2 o2 = unpack2(acc2[rp][2]);
        float2 o3 = unpack2(acc2[rp][3]);
#pragma unroll
        for (int hh = 0; hh < 2; hh++) {
            int tok = tok0 + ty * 16 + rp * 2 + hh;
            float4 o;
            o.x = (hh ? o0.y : o0.x) + bias.x;
            o.y = (hh ? o1.y : o1.x) + bias.y;
            o.z = (hh ? o2.y : o2.x) + bias.z;
            o.w = (hh ? o3.y : o3.x) + bias.w;
            *(float4*)&g_XW[(size_t)tok * 2048 + c0 + tx * 4] = o;
        }
    }
}

// ---------------- word LSTM helpers: smem layout ----------------
// wsT: [16 cols][520] transposed weight slice              -> 33280 B
// hs:  [32][516] h_prev, b-major, padded row               -> 66048 B
#define WORD_WS_STRIDE 520
#define WORD_WS_FLOATS (16 * WORD_WS_STRIDE)
#define WORD_HS_STRIDE 516
#define WORD_SMEM_BYTES ((WORD_WS_FLOATS + NB * WORD_HS_STRIDE) * 4)

__device__ __forceinline__ void word_fill_ws(float* wsT, int c0, int tid)
{
    for (int idx = tid; idx < 512 * 16; idx += 128) {
        int k = idx >> 4, j = idx & 15;
        wsT[j * WORD_WS_STRIDE + k] = g_WwhhT[k * 2048 + c0 + j];
    }
}

// Fill hs[b][k] from g_Hsave(t-1) with float4 loads/stores (32 LDG.128/thread).
__device__ __forceinline__ void word_fill_hs(float* hs, int t, int tid)
{
    if (t == 0) {
        for (int i = tid; i < NB * WORD_HS_STRIDE; i += 128) hs[i] = 0.f;
    } else {
#pragma unroll 4
        for (int i = tid; i < 4096; i += 128) {            // 4096 float4 = 32b x 128
            int bb = i >> 7, k4 = i & 127;
            float4 v = *(const float4*)&g_Hsave[(size_t)((bb << 10) + (t - 1)) * NH + k4 * 4];
            *(float4*)&hs[bb * WORD_HS_STRIDE + k4 * 4] = v;
        }
    }
}

// Inner product: 4 gate-cols (ul) over 512 k; packed f32x2, both operands pair
// naturally along k (wsT is [col][k]). Pairwise sums + horizontal add at the end.
__device__ __forceinline__ float4 word_dot(const float* hrow, const float* wsT, int ul)
{
    const float* w0 = wsT + (ul * 4 + 0) * WORD_WS_STRIDE;
    const float* w1 = wsT + (ul * 4 + 1) * WORD_WS_STRIDE;
    const float* w2 = wsT + (ul * 4 + 2) * WORD_WS_STRIDE;
    const float* w3 = wsT + (ul * 4 + 3) * WORD_WS_STRIDE;
    unsigned long long a0 = 0ull, a1 = 0ull, a2 = 0ull, a3 = 0ull;
#pragma unroll 8
    for (int k = 0; k < 512; k += 4) {
        ulonglong2 h2 = *(const ulonglong2*)&hrow[k];
        ulonglong2 p0 = *(const ulonglong2*)&w0[k];
        ulonglong2 p1 = *(const ulonglong2*)&w1[k];
        ulonglong2 p2 = *(const ulonglong2*)&w2[k];
        ulonglong2 p3 = *(const ulonglong2*)&w3[k];
        ffma2(a0, h2.x, p0.x); ffma2(a0, h2.y, p0.y);
        ffma2(a1, h2.x, p1.x); ffma2(a1, h2.y, p1.y);
        ffma2(a2, h2.x, p2.x); ffma2(a2, h2.y, p2.y);
        ffma2(a3, h2.x, p3.x); ffma2(a3, h2.y, p3.y);
    }
    float2 f0 = unpack2(a0), f1 = unpack2(a1), f2 = unpack2(a2), f3 = unpack2(a3);
    return make_float4(f0.x + f0.y, f1.x + f1.y, f2.x + f2.y, f3.x + f3.y);
}

// ---------------- word LSTM, cooperative (1 launch, grid.sync) ----------------
// 128 CTAs; CTA owns 16 gate-cols (4 units) x all 32 batches. c-state in register.
__global__ __launch_bounds__(128, 1)
void word_coop_kernel(int /*dummy*/)
{
    cg::grid_group grid = cg::this_grid();

    extern __shared__ float sm[];
    float* wsT = sm;
    float* hs  = sm + WORD_WS_FLOATS;

    const int tid = threadIdx.x;
    const int b  = tid >> 2;
    const int ul = tid & 3;
    const int c0 = blockIdx.x * 16;
    const int ug = (c0 >> 2) + ul;                 // global unit 0..511

    word_fill_ws(wsT, c0, tid);

    float c = 0.f;
    for (int t = 0; t < NS; t++) {
        word_fill_hs(hs, t, tid);
        __syncthreads();

        float4 a = *(const float4*)&g_XW[(size_t)((b << 10) + t) * 2048 + c0 + ul * 4];
        float4 acc = word_dot(&hs[b * WORD_HS_STRIDE], wsT, ul);

        float gi = acc.x + a.x;     // bias already folded into XW
        float gf = acc.y + a.y;
        float gg = acc.z + a.z;
        float go = acc.w + a.w;
        c = sigm_(gf) * c + sigm_(gi) * tanh_(gg);
        float h = sigm_(go) * tanh_(c);
        g_Hsave[(size_t)((b << 10) + t) * NH + ug] = h;

        grid.sync();   // grid-wide barrier with memory ordering; also fences hs reuse
    }
}

// ---------------- word LSTM fallback: one launch per step ----------------
__global__ __launch_bounds__(128, 1)
void word_step_kernel(int t)
{
    extern __shared__ float sm[];
    float* wsT = sm;
    float* hs  = sm + WORD_WS_FLOATS;

    const int tid = threadIdx.x;
    const int b  = tid >> 2;
    const int ul = tid & 3;
    const int c0 = blockIdx.x * 16;
    const int ug = (c0 >> 2) + ul;

    word_fill_ws(wsT, c0, tid);
    word_fill_hs(hs, t, tid);
    __syncthreads();

    float4 a = *(const float4*)&g_XW[(size_t)((b << 10) + t) * 2048 + c0 + ul * 4];
    float4 acc = word_dot(&hs[b * WORD_HS_STRIDE], wsT, ul);

    float gi = acc.x + a.x;
    float gf = acc.y + a.y;
    float gg = acc.z + a.z;
    float go = acc.w + a.w;
    float c = (t == 0) ? 0.f : g_Cw[b * NH + ug];
    c = sigm_(gf) * c + sigm_(gi) * tanh_(gg);
    float h = sigm_(go) * tanh_(c);
    g_Cw[b * NH + ug] = c;
    g_Hsave[(size_t)((b << 10) + t) * NH + ug] = h;
}

// ---------------- logits + log_softmax ----------------
// Block: 256 thr = 4 tokens x 64 tags. Wt transposed in smem [k][64].
__global__ __launch_bounds__(256, 1)
void logits_kernel(const float* __restrict__ Wt, const float* __restrict__ bt,
                   float* __restrict__ out)
{
    extern __shared__ float sm[];
    float* Wts = sm;               // [512][65]
    float* hs  = sm + 512 * 65;    // [4][512]
    __shared__ float sl[4][64];

    const int tid = threadIdx.x;
    for (int idx = tid; idx < 512 * 64; idx += 256) {
        int tg = idx >> 9, k = idx & 511;
        Wts[k * 65 + tg] = (tg < NT) ? Wt[tg * NH + k] : 0.f;
    }
    const int tokl = tid >> 6, tag = tid & 63;
    const int wid = tid >> 5, lane = tid & 31;
    float btv = (tag < NT) ? bt[tag] : 0.f;

    for (int tb = blockIdx.x; tb < NTOK / 4; tb += gridDim.x) {
        __syncthreads();
        for (int idx = tid; idx < 2048; idx += 256) {
            int tk = idx >> 9, k = idx & 511;
            hs[tk * 512 + k] = g_Hsave[(size_t)(tb * 4 + tk) * NH + k];
        }
        __syncthreads();
        float acc = 0.f;
#pragma unroll 8
        for (int k = 0; k < 512; k++)
            acc += hs[tokl * 512 + k] * Wts[k * 65 + tag];
        sl[tokl][tag] = (tag < NT) ? (acc + btv) : -1e30f;
        __syncthreads();
        if (wid < 4) {
            float l0 = sl[wid][lane], l1 = sl[wid][lane + 32];
            float m = fmaxf(l0, l1);
#pragma unroll
            for (int o = 16; o; o >>= 1) m = fmaxf(m, __shfl_xor_sync(0xffffffffu, m, o));
            float s = __expf(l0 - m) + __expf(l1 - m);
#pragma unroll
            for (int o = 16; o; o >>= 1) s += __shfl_xor_sync(0xffffffffu, s, o);
            float lse = m + __logf(s);
            int n = tb * 4 + wid;
            for (int j = lane; j < NT; j += 32)
                out[(size_t)n * NT + j] = sl[wid][j] - lse;
        }
    }
}

// ---------------- launch ----------------
extern "C" void kernel_launch(void* const* d_in, const int* in_sizes, int n_in,
                              void* d_out, int out_size)
{
    const int*   char_idx = (const int*)d_in[0];
    const int*   word_idx = (const int*)d_in[1];
    const float* char_emb = (const float*)d_in[2];
    const float* word_emb = (const float*)d_in[3];
    const float* Wc_ih    = (const float*)d_in[4];
    const float* Wc_hh    = (const float*)d_in[5];
    const float* bc       = (const float*)d_in[6];
    const float* Ww_ih    = (const float*)d_in[7];
    const float* Ww_hh    = (const float*)d_in[8];
    const float* bw       = (const float*)d_in[9];
    const float* Wt       = (const float*)d_in[10];
    const float* bt       = (const float*)d_in[11];
    float* out = (float*)d_out;

    const int word_smem   = WORD_SMEM_BYTES;             // 99328 B
    const int logits_smem = (512 * 65 + 4 * 512) * 4;    // 141312 B
    cudaFuncSetAttribute(word_coop_kernel,
                         cudaFuncAttributeMaxDynamicSharedMemorySize, word_smem);
    cudaFuncSetAttribute(word_step_kernel,
                         cudaFuncAttributeMaxDynamicSharedMemorySize, word_smem);
    cudaFuncSetAttribute(logits_kernel,
                         cudaFuncAttributeMaxDynamicSharedMemorySize, logits_smem);

    // Deterministic host-side decision: cooperative path only if the device
    // guarantees 128 co-resident CTAs (pure queries, capture-legal).
    int dev = 0;
    cudaGetDevice(&dev);
    int numSM = 0, coopAttr = 0, perSM = 0;
    cudaDeviceGetAttribute(&numSM, cudaDevAttrMultiProcessorCount, dev);
    cudaDeviceGetAttribute(&coopAttr, cudaDevAttrCooperativeLaunch, dev);
    cudaOccupancyMaxActiveBlocksPerMultiprocessor(&perSM, word_coop_kernel, 128, word_smem);
    const bool coop_ok = (coopAttr != 0) && (perSM >= 1) && (numSM >= 128);

    prep_all_kernel<<<4096, 256>>>(Wc_ih, Wc_hh, bc, Ww_ih, Ww_hh, bw);

    for (int t = 0; t < NC; t++)
        char_step_kernel<<<dim3(NTOK / 64, 4), 256>>>(char_idx, char_emb, t);

    xw_kernel<<<dim3(NTOK / 64, 8), 256>>>(word_idx, word_emb);

    if (coop_ok) {
        int dummy = 0;
        void* kargs[] = { &dummy };
        cudaLaunchCooperativeKernel((void*)word_coop_kernel,
                                    dim3(128), dim3(128),
                                    kargs, (size_t)word_smem, (cudaStream_t)0);
    } else {
        for (int t = 0; t < NS; t++)
            word_step_kernel<<<128, 128, word_smem>>>(t);
    }

    logits_kernel<<<148, 256, logits_smem>>>(Wt, bt, out);
}

// round 10
// speedup vs baseline: 1.7501x; 1.7501x over previous
#include <cuda_runtime.h>
#include <cuda_bf16.h>
#include <cooperative_groups.h>
#include <stdint.h>

namespace cg = cooperative_groups;

// Problem dims
#define NB 32
#define NS 1024
#define NC 12
#define NE 256
#define NH 512
#define NT 50
#define NTOK (NB*NS)          // 32768

// ---------------- device scratch (allocation-free) ----------------
__device__ float g_WcihT[NE * 4 * NE];            // [k=256][1024] col 4u+g <- row g*256+u
__device__ float g_WchhT[NE * 4 * NE];
__device__ float g_bcp[4 * NE];
__device__ float g_WwihT[2 * NE * 4 * NH];        // [k=512][2048]
__device__ float g_WwhhT[NH * 4 * NH];            // [k=512][2048]
__device__ float g_bwp[4 * NH];

__device__ float g_HcA[NTOK * NE];                // char h ping
__device__ float g_HcB[NTOK * NE];                // char h pong (holds final char_feat)
__device__ float g_Cc [NTOK * NE];                // char c state
__device__ float g_XW [(size_t)NTOK * 4 * NH];    // word-input preacts + bias, [n][2048]
__device__ float g_Hsave[(size_t)NTOK * NH];      // word hidden trace [n][512]
__device__ float g_Cw [NB * NH];                  // word c state (fallback path only)

// ---------------- math helpers ----------------
__device__ __forceinline__ float sigm_(float x) {
    return __fdividef(1.f, 1.f + __expf(-x));
}
__device__ __forceinline__ float tanh_(float x) {
    return __fdividef(2.f, 1.f + __expf(-2.f * x)) - 1.f;
}

// ---------------- packed f32x2 helpers (sm_100+) ----------------
__device__ __forceinline__ unsigned long long splat2(float x) {
    unsigned long long r;
    asm("mov.b64 %0, {%1, %1};" : "=l"(r) : "f"(x));
    return r;
}
__device__ __forceinline__ void ffma2(unsigned long long& d,
                                      unsigned long long a, unsigned long long b) {
    asm("fma.rn.f32x2 %0, %1, %2, %0;" : "+l"(d) : "l"(a), "l"(b));
}
__device__ __forceinline__ float2 unpack2(unsigned long long v) {
    float2 f;
    asm("mov.b64 {%0, %1}, %2;" : "=f"(f.x), "=f"(f.y) : "l"(v));
    return f;
}

// ---------------- prep: permute/transpose weights ----------------
__global__ void prep_all_kernel(const float* __restrict__ Wc_ih,
                                const float* __restrict__ Wc_hh,
                                const float* __restrict__ bc,
                                const float* __restrict__ Ww_ih,
                                const float* __restrict__ Ww_hh,
                                const float* __restrict__ bw)
{
    const int stride = gridDim.x * blockDim.x;
    for (int idx = blockIdx.x * blockDim.x + threadIdx.x; idx < 1048576; idx += stride) {
        // word weights: [k=512][c=2048], WT[k*2048 + (4u+g)] = W[(g*512+u)*Kdim + k]
        {
            int c = idx & 2047, k = idx >> 11;      // k in [0,512)
            int u = c >> 2, g = c & 3;
            g_WwihT[idx] = Ww_ih[(g * NH + u) * (2 * NE) + k];
            g_WwhhT[idx] = Ww_hh[(g * NH + u) * NH + k];
        }
        // char weights: [k=256][c=1024]
        if (idx < 262144) {
            int c = idx & 1023, k = idx >> 10;      // k in [0,256)
            int u = c >> 2, g = c & 3;
            g_WcihT[idx] = Wc_ih[(g * NE + u) * NE + k];
            g_WchhT[idx] = Wc_hh[(g * NE + u) * NE + k];
        }
        if (idx < 2048) {
            int u = idx >> 2, g = idx & 3;
            g_bwp[idx] = bw[g * NH + u];
        }
        if (idx < 1024) {
            int u = idx >> 2, g = idx & 3;
            g_bcp[idx] = bc[g * NE + u];
        }
    }
}

// ---------------- char LSTM step (FFMA2 inner loop; R8-verified) ----------------
__global__ __launch_bounds__(256, 2)
void char_step_kernel(const int* __restrict__ char_idx,
                      const float* __restrict__ char_emb, int t)
{
    __shared__ float Xs[16][68];     // [k][token], padded
    __shared__ float Ws[16][260];    // [k][col],   padded
    __shared__ int   idxs[64];

    const int tid = threadIdx.x;
    const int tx = tid & 63;
    const int ty = tid >> 6;
    const int tok0 = blockIdx.x * 64;
    const int c0 = blockIdx.y * 256;

    float* hnew        = (t & 1) ? g_HcB : g_HcA;
    const float* hprev = (t & 1) ? g_HcA : g_HcB;

    unsigned long long acc2[8][4];   // [row-pair][col], packed f32x2
#pragma unroll
    for (int rp = 0; rp < 8; rp++) {
        acc2[rp][0] = 0ull; acc2[rp][1] = 0ull; acc2[rp][2] = 0ull; acc2[rp][3] = 0ull;
    }

    if (tid < 64) idxs[tid] = char_idx[(tok0 + tid) * NC + t];
    __syncthreads();

    const int npass = (t == 0) ? 1 : 2;
    for (int pass = 0; pass < npass; pass++) {
        const float* W = pass ? g_WchhT : g_WcihT;
        for (int kc = 0; kc < 16; kc++) {
            const int k0 = kc * 16;
            {
                int tok = tid >> 2, kq = tid & 3;
                float4 v;
                if (pass == 0)
                    v = *(const float4*)&char_emb[idxs[tok] * NE + k0 + kq * 4];
                else
                    v = *(const float4*)&hprev[(tok0 + tok) * NE + k0 + kq * 4];
                Xs[kq * 4 + 0][tok] = v.x;
                Xs[kq * 4 + 1][tok] = v.y;
                Xs[kq * 4 + 2][tok] = v.z;
                Xs[kq * 4 + 3][tok] = v.w;
            }
#pragma unroll
            for (int j = 0; j < 4; j++) {
                int f = tid + j * 256;
                int kk = f >> 6, cq = f & 63;
                *(float4*)&Ws[kk][cq * 4] =
                    *(const float4*)&W[(k0 + kk) * 1024 + c0 + cq * 4];
            }
            __syncthreads();
#pragma unroll
            for (int k = 0; k < 16; k++) {
                float4 b = *(float4*)&Ws[k][tx * 4];
                unsigned long long bs0 = splat2(b.x);
                unsigned long long bs1 = splat2(b.y);
                unsigned long long bs2 = splat2(b.z);
                unsigned long long bs3 = splat2(b.w);
                ulonglong2 A0 = *(const ulonglong2*)&Xs[k][ty * 16 + 0];
                ulonglong2 A1 = *(const ulonglong2*)&Xs[k][ty * 16 + 4];
                ulonglong2 A2 = *(const ulonglong2*)&Xs[k][ty * 16 + 8];
                ulonglong2 A3 = *(const ulonglong2*)&Xs[k][ty * 16 + 12];
                unsigned long long ap[8] = {A0.x, A0.y, A1.x, A1.y, A2.x, A2.y, A3.x, A3.y};
#pragma unroll
                for (int rp = 0; rp < 8; rp++) {
                    ffma2(acc2[rp][0], ap[rp], bs0);
                    ffma2(acc2[rp][1], ap[rp], bs1);
                    ffma2(acc2[rp][2], ap[rp], bs2);
                    ffma2(acc2[rp][3], ap[rp], bs3);
                }
            }
            __syncthreads();
        }
    }

    const int u = (c0 >> 2) + tx;                  // global unit 0..255
    float4 bias = *(const float4*)&g_bcp[c0 + tx * 4];
#pragma unroll
    for (int rp = 0; rp < 8; rp++) {
        float2 gi2 = unpack2(acc2[rp][0]);
        float2 gf2 = unpack2(acc2[rp][1]);
        float2 gg2 = unpack2(acc2[rp][2]);
        float2 go2 = unpack2(acc2[rp][3]);
#pragma unroll
        for (int hh = 0; hh < 2; hh++) {
            int tok = tok0 + ty * 16 + rp * 2 + hh;
            float gi = (hh ? gi2.y : gi2.x) + bias.x;
            float gf = (hh ? gf2.y : gf2.x) + bias.y;
            float gg = (hh ? gg2.y : gg2.x) + bias.z;
            float go = (hh ? go2.y : go2.x) + bias.w;
            float cp = (t == 0) ? 0.f : g_Cc[tok * NE + u];
            float cn = sigm_(gf) * cp + sigm_(gi) * tanh_(gg);
            float h  = sigm_(go) * tanh_(cn);
            g_Cc[tok * NE + u] = cn;
            hnew[tok * NE + u] = h;
        }
    }
}

// ---------------- word-input GEMM: XW = [we ; char_feat] @ WwihT + bw (FFMA2) -------
__global__ __launch_bounds__(256, 2)
void xw_kernel(const int* __restrict__ word_idx, const float* __restrict__ word_emb)
{
    __shared__ float Xs[16][68];
    __shared__ float Ws[16][260];
    __shared__ int   idxs[64];

    const int tid = threadIdx.x;
    const int tx = tid & 63;
    const int ty = tid >> 6;
    const int tok0 = blockIdx.x * 64;
    const int c0 = blockIdx.y * 256;

    unsigned long long acc2[8][4];
#pragma unroll
    for (int rp = 0; rp < 8; rp++) {
        acc2[rp][0] = 0ull; acc2[rp][1] = 0ull; acc2[rp][2] = 0ull; acc2[rp][3] = 0ull;
    }

    if (tid < 64) idxs[tid] = word_idx[tok0 + tid];
    __syncthreads();

    for (int kc = 0; kc < 32; kc++) {
        const int k0 = kc * 16;
        {
            int tok = tid >> 2, kq = tid & 3;
            float4 v;
            if (kc < 16)
                v = *(const float4*)&word_emb[(size_t)idxs[tok] * NE + k0 + kq * 4];
            else
                v = *(const float4*)&g_HcB[(tok0 + tok) * NE + (k0 - NE) + kq * 4];
            Xs[kq * 4 + 0][tok] = v.x;
            Xs[kq * 4 + 1][tok] = v.y;
            Xs[kq * 4 + 2][tok] = v.z;
            Xs[kq * 4 + 3][tok] = v.w;
        }
#pragma unroll
        for (int j = 0; j < 4; j++) {
            int f = tid + j * 256;
            int kk = f >> 6, cq = f & 63;
            *(float4*)&Ws[kk][cq * 4] =
                *(const float4*)&g_WwihT[(k0 + kk) * 2048 + c0 + cq * 4];
        }
        __syncthreads();
#pragma unroll
        for (int k = 0; k < 16; k++) {
            float4 b = *(float4*)&Ws[k][tx * 4];
            unsigned long long bs0 = splat2(b.x);
            unsigned long long bs1 = splat2(b.y);
            unsigned long long bs2 = splat2(b.z);
            unsigned long long bs3 = splat2(b.w);
            ulonglong2 A0 = *(const ulonglong2*)&Xs[k][ty * 16 + 0];
            ulonglong2 A1 = *(const ulonglong2*)&Xs[k][ty * 16 + 4];
            ulonglong2 A2 = *(const ulonglong2*)&Xs[k][ty * 16 + 8];
            ulonglong2 A3 = *(const ulonglong2*)&Xs[k][ty * 16 + 12];
            unsigned long long ap[8] = {A0.x, A0.y, A1.x, A1.y, A2.x, A2.y, A3.x, A3.y};
#pragma unroll
            for (int rp = 0; rp < 8; rp++) {
                ffma2(acc2[rp][0], ap[rp], bs0);
                ffma2(acc2[rp][1], ap[rp], bs1);
                ffma2(acc2[rp][2], ap[rp], bs2);
                ffma2(acc2[rp][3], ap[rp], bs3);
            }
        }
        __syncthreads();
    }

    float4 bias = *(const float4*)&g_bwp[c0 + tx * 4];
#pragma unroll
    for (int rp = 0; rp < 8; rp++) {
        float2 o0 = unpack2(acc2[rp][0]);
        float2 o1 = unpack2(acc2[rp][1]);
        float2 o2 = unpack2(acc2[rp][2]);
        float2 o3 = unpack2(acc2[rp][3]);
#pragma unroll
        for (int hh = 0; hh < 2; hh++) {
            int tok = tok0 + ty * 16 + rp * 2 + hh;
            float4 o;
            o.x = (hh ? o0.y : o0.x) + bias.x;
            o.y = (hh ? o1.y : o1.x) + bias.y;
            o.z = (hh ? o2.y : o2.x) + bias.z;
            o.w = (hh ? o3.y : o3.x) + bias.w;
            *(float4*)&g_XW[(size_t)tok * 2048 + c0 + tx * 4] = o;
        }
    }
}

// ---------------- word LSTM: smem layout (R7-proven, conflict-free) ----------------
// ws: [512][20] weight slice (16 cols padded to 20)    -> 40960 B
// hs: [32][516] h_prev, b-major, padded row            -> 66048 B
// ps: [128][4]  k-half partials                        ->  2048 B
#define WORD_WS_FLOATS (512 * 20)
#define WORD_HS_STRIDE 516
#define WORD_HS_FLOATS (NB * WORD_HS_STRIDE)
#define WORD_PS_FLOATS (128 * 4)
#define WORD_SMEM_BYTES ((WORD_WS_FLOATS + WORD_HS_FLOATS + WORD_PS_FLOATS) * 4)
#define WORD_THREADS 256

__device__ __forceinline__ void word_fill_ws(float* ws, int c0, int tid)
{
    for (int idx = tid; idx < 512 * 16; idx += WORD_THREADS) {
        int k = idx >> 4, j = idx & 15;
        ws[k * 20 + j] = g_WwhhT[k * 2048 + c0 + j];
    }
}

// Fill hs[b][k] from g_Hsave(t-1) with float4 loads/stores.
__device__ __forceinline__ void word_fill_hs(float* hs, int t, int tid)
{
    if (t == 0) {
        for (int i = tid; i < WORD_HS_FLOATS; i += WORD_THREADS) hs[i] = 0.f;
    } else {
#pragma unroll 4
        for (int i = tid; i < 4096; i += WORD_THREADS) {   // 4096 float4 = 32b x 128
            int bb = i >> 7, k4 = i & 127;
            float4 v = *(const float4*)&g_Hsave[(size_t)((bb << 10) + (t - 1)) * NH + k4 * 4];
            *(float4*)&hs[bb * WORD_HS_STRIDE + k4 * 4] = v;
        }
    }
}

// Half-range inner product: 4 gate-cols (ul) over k in [k0, k0+256). R7 layout.
__device__ __forceinline__ float4 word_dot_half(const float* hrow, const float* ws,
                                                int ul, int k0)
{
    float4 acc = make_float4(0.f, 0.f, 0.f, 0.f);
#pragma unroll 8
    for (int k = k0; k < k0 + 256; k += 4) {
        float4 h4 = *(const float4*)&hrow[k];
        float4 w0 = *(const float4*)&ws[(k + 0) * 20 + ul * 4];
        float4 w1 = *(const float4*)&ws[(k + 1) * 20 + ul * 4];
        float4 w2 = *(const float4*)&ws[(k + 2) * 20 + ul * 4];
        float4 w3 = *(const float4*)&ws[(k + 3) * 20 + ul * 4];
        acc.x += h4.x * w0.x; acc.y += h4.x * w0.y; acc.z += h4.x * w0.z; acc.w += h4.x * w0.w;
        acc.x += h4.y * w1.x; acc.y += h4.y * w1.y; acc.z += h4.y * w1.z; acc.w += h4.y * w1.w;
        acc.x += h4.z * w2.x; acc.y += h4.z * w2.y; acc.z += h4.z * w2.z; acc.w += h4.z * w2.w;
        acc.x += h4.w * w3.x; acc.y += h4.w * w3.y; acc.z += h4.w * w3.z; acc.w += h4.w * w3.w;
    }
    return acc;
}

// Shared per-step body for coop and fallback kernels. Returns updated c.
// tid layout: khalf = tid>>7 (k-range), r = tid&127, b = r>>2, ul = r&3.
// All __syncthreads are unconditional (uniform control flow for all 256 threads).
__device__ __forceinline__ float word_step_body(float* ws, float* hs, float* ps,
                                                int t, int tid, int c0, float c)
{
    const int khalf = tid >> 7;
    const int r  = tid & 127;
    const int b  = r >> 2;
    const int ul = r & 3;
    const int ug = (c0 >> 2) + ul;

    word_fill_hs(hs, t, tid);
    __syncthreads();

    float4 acc = word_dot_half(&hs[b * WORD_HS_STRIDE], ws, ul, khalf * 256);

    if (khalf == 1) *(float4*)&ps[r * 4] = acc;
    __syncthreads();

    if (khalf == 0) {
        float4 p = *(const float4*)&ps[r * 4];
        float4 a = *(const float4*)&g_XW[(size_t)((b << 10) + t) * 2048 + c0 + ul * 4];
        float gi = acc.x + p.x + a.x;     // bias already folded into XW
        float gf = acc.y + p.y + a.y;
        float gg = acc.z + p.z + a.z;
        float go = acc.w + p.w + a.w;
        c = sigm_(gf) * c + sigm_(gi) * tanh_(gg);
        float h = sigm_(go) * tanh_(c);
        g_Hsave[(size_t)((b << 10) + t) * NH + ug] = h;
    }
    return c;
}

// ---------------- word LSTM, cooperative (1 launch, grid.sync) ----------------
// 128 CTAs x 256 thr; CTA owns 16 gate-cols x all 32 batches; k split in halves.
__global__ __launch_bounds__(WORD_THREADS, 1)
void word_coop_kernel(int /*dummy*/)
{
    cg::grid_group grid = cg::this_grid();

    extern __shared__ float sm[];
    float* ws = sm;
    float* hs = sm + WORD_WS_FLOATS;
    float* ps = hs + WORD_HS_FLOATS;

    const int tid = threadIdx.x;
    const int c0 = blockIdx.x * 16;

    word_fill_ws(ws, c0, tid);

    float c = 0.f;
    for (int t = 0; t < NS; t++) {
        c = word_step_body(ws, hs, ps, t, tid, c0, c);
        grid.sync();   // grid-wide barrier with memory ordering; also fences hs reuse
    }
}

// ---------------- word LSTM fallback: one launch per step ----------------
__global__ __launch_bounds__(WORD_THREADS, 1)
void word_step_kernel(int t)
{
    extern __shared__ float sm[];
    float* ws = sm;
    float* hs = sm + WORD_WS_FLOATS;
    float* ps = hs + WORD_HS_FLOATS;

    const int tid = threadIdx.x;
    const int c0 = blockIdx.x * 16;
    const int khalf = tid >> 7;
    const int r = tid & 127;
    const int b = r >> 2;
    const int ul = r & 3;
    const int ug = (c0 >> 2) + ul;

    word_fill_ws(ws, c0, tid);

    float c = (t == 0 || khalf) ? 0.f : g_Cw[b * NH + ug];
    c = word_step_body(ws, hs, ps, t, tid, c0, c);
    if (khalf == 0) g_Cw[b * NH + ug] = c;
}

// ---------------- logits + log_softmax ----------------
__global__ __launch_bounds__(256, 1)
void logits_kernel(const float* __restrict__ Wt, const float* __restrict__ bt,
                   float* __restrict__ out)
{
    extern __shared__ float sm[];
    float* Wts = sm;               // [512][65]
    float* hs  = sm + 512 * 65;    // [4][512]
    __shared__ float sl[4][64];

    const int tid = threadIdx.x;
    for (int idx = tid; idx < 512 * 64; idx += 256) {
        int tg = idx >> 9, k = idx & 511;
        Wts[k * 65 + tg] = (tg < NT) ? Wt[tg * NH + k] : 0.f;
    }
    const int tokl = tid >> 6, tag = tid & 63;
    const int wid = tid >> 5, lane = tid & 31;
    float btv = (tag < NT) ? bt[tag] : 0.f;

    for (int tb = blockIdx.x; tb < NTOK / 4; tb += gridDim.x) {
        __syncthreads();
        for (int idx = tid; idx < 2048; idx += 256) {
            int tk = idx >> 9, k = idx & 511;
            hs[tk * 512 + k] = g_Hsave[(size_t)(tb * 4 + tk) * NH + k];
        }
        __syncthreads();
        float acc = 0.f;
#pragma unroll 8
        for (int k = 0; k < 512; k++)
            acc += hs[tokl * 512 + k] * Wts[k * 65 + tag];
        sl[tokl][tag] = (tag < NT) ? (acc + btv) : -1e30f;
        __syncthreads();
        if (wid < 4) {
            float l0 = sl[wid][lane], l1 = sl[wid][lane + 32];
            float m = fmaxf(l0, l1);
#pragma unroll
            for (int o = 16; o; o >>= 1) m = fmaxf(m, __shfl_xor_sync(0xffffffffu, m, o));
            float s = __expf(l0 - m) + __expf(l1 - m);
#pragma unroll
            for (int o = 16; o; o >>= 1) s += __shfl_xor_sync(0xffffffffu, s, o);
            float lse = m + __logf(s);
            int n = tb * 4 + wid;
            for (int j = lane; j < NT; j += 32)
                out[(size_t)n * NT + j] = sl[wid][j] - lse;
        }
    }
}

// ---------------- launch ----------------
extern "C" void kernel_launch(void* const* d_in, const int* in_sizes, int n_in,
                              void* d_out, int out_size)
{
    const int*   char_idx = (const int*)d_in[0];
    const int*   word_idx = (const int*)d_in[1];
    const float* char_emb = (const float*)d_in[2];
    const float* word_emb = (const float*)d_in[3];
    const float* Wc_ih    = (const float*)d_in[4];
    const float* Wc_hh    = (const float*)d_in[5];
    const float* bc       = (const float*)d_in[6];
    const float* Ww_ih    = (const float*)d_in[7];
    const float* Ww_hh    = (const float*)d_in[8];
    const float* bw       = (const float*)d_in[9];
    const float* Wt       = (const float*)d_in[10];
    const float* bt       = (const float*)d_in[11];
    float* out = (float*)d_out;

    const int word_smem   = WORD_SMEM_BYTES;             // 109056 B
    const int logits_smem = (512 * 65 + 4 * 512) * 4;    // 141312 B
    cudaFuncSetAttribute(word_coop_kernel,
                         cudaFuncAttributeMaxDynamicSharedMemorySize, word_smem);
    cudaFuncSetAttribute(word_step_kernel,
                         cudaFuncAttributeMaxDynamicSharedMemorySize, word_smem);
    cudaFuncSetAttribute(logits_kernel,
                         cudaFuncAttributeMaxDynamicSharedMemorySize, logits_smem);

    // Deterministic host-side decision: cooperative path only if the device
    // guarantees 128 co-resident CTAs (pure queries, capture-legal).
    int dev = 0;
    cudaGetDevice(&dev);
    int numSM = 0, coopAttr = 0, perSM = 0;
    cudaDeviceGetAttribute(&numSM, cudaDevAttrMultiProcessorCount, dev);
    cudaDeviceGetAttribute(&coopAttr, cudaDevAttrCooperativeLaunch, dev);
    cudaOccupancyMaxActiveBlocksPerMultiprocessor(&perSM, word_coop_kernel,
                                                  WORD_THREADS, word_smem);
    const bool coop_ok = (coopAttr != 0) && (perSM >= 1) && (numSM >= 128);

    prep_all_kernel<<<4096, 256>>>(Wc_ih, Wc_hh, bc, Ww_ih, Ww_hh, bw);

    for (int t = 0; t < NC; t++)
        char_step_kernel<<<dim3(NTOK / 64, 4), 256>>>(char_idx, char_emb, t);

    xw_kernel<<<dim3(NTOK / 64, 8), 256>>>(word_idx, word_emb);

    if (coop_ok) {
        int dummy = 0;
        void* kargs[] = { &dummy };
        cudaLaunchCooperativeKernel((void*)word_coop_kernel,
                                    dim3(128), dim3(WORD_THREADS),
                                    kargs, (size_t)word_smem, (cudaStream_t)0);
    } else {
        for (int t = 0; t < NS; t++)
            word_step_kernel<<<128, WORD_THREADS, word_smem>>>(t);
    }

    logits_kernel<<<148, 256, logits_smem>>>(Wt, bt, out);
}

// round 11
// speedup vs baseline: 1.8452x; 1.0543x over previous
#include <cuda_runtime.h>
#include <cuda_bf16.h>
#include <cooperative_groups.h>
#include <stdint.h>

namespace cg = cooperative_groups;

// Problem dims
#define NB 32
#define NS 1024
#define NC 12
#define NE 256
#define NH 512
#define NT 50
#define NTOK (NB*NS)          // 32768

// ---------------- device scratch (allocation-free) ----------------
__device__ float g_WcihT[NE * 4 * NE];            // [k=256][1024] col 4u+g <- row g*256+u
__device__ float g_WchhT[NE * 4 * NE];
__device__ float g_bcp[4 * NE];
__device__ float g_WwihT[2 * NE * 4 * NH];        // [k=512][2048]
__device__ float g_WwhhT[NH * 4 * NH];            // [k=512][2048]
__device__ float g_bwp[4 * NH];

__device__ float g_HcA[NTOK * NE];                // char h ping
__device__ float g_HcB[NTOK * NE];                // char h pong (holds final char_feat)
__device__ float g_Cc [NTOK * NE];                // char c state
__device__ float g_XW [(size_t)NTOK * 4 * NH];    // word-input preacts + bias, [n][2048]
__device__ float g_Hsave[(size_t)NTOK * NH];      // word hidden trace [n][512]
__device__ float g_Cw [NB * NH];                  // word c state (fallback path only)
__device__ unsigned int g_bar4[4];                // per-subgrid monotonic barrier counters

// ---------------- math helpers ----------------
__device__ __forceinline__ float sigm_(float x) {
    return __fdividef(1.f, 1.f + __expf(-x));
}
__device__ __forceinline__ float tanh_(float x) {
    return __fdividef(2.f, 1.f + __expf(-2.f * x)) - 1.f;
}

// ---------------- packed f32x2 helpers (sm_100+) ----------------
__device__ __forceinline__ unsigned long long splat2(float x) {
    unsigned long long r;
    asm("mov.b64 %0, {%1, %1};" : "=l"(r) : "f"(x));
    return r;
}
__device__ __forceinline__ void ffma2(unsigned long long& d,
                                      unsigned long long a, unsigned long long b) {
    asm("fma.rn.f32x2 %0, %1, %2, %0;" : "+l"(d) : "l"(a), "l"(b));
}
__device__ __forceinline__ float2 unpack2(unsigned long long v) {
    float2 f;
    asm("mov.b64 {%0, %1}, %2;" : "=f"(f.x), "=f"(f.y) : "l"(v));
    return f;
}

// ---------------- prep: permute/transpose weights, zero barriers ----------------
__global__ void prep_all_kernel(const float* __restrict__ Wc_ih,
                                const float* __restrict__ Wc_hh,
                                const float* __restrict__ bc,
                                const float* __restrict__ Ww_ih,
                                const float* __restrict__ Ww_hh,
                                const float* __restrict__ bw)
{
    const int stride = gridDim.x * blockDim.x;
    for (int idx = blockIdx.x * blockDim.x + threadIdx.x; idx < 1048576; idx += stride) {
        // word weights: [k=512][c=2048], WT[k*2048 + (4u+g)] = W[(g*512+u)*Kdim + k]
        {
            int c = idx & 2047, k = idx >> 11;      // k in [0,512)
            int u = c >> 2, g = c & 3;
            g_WwihT[idx] = Ww_ih[(g * NH + u) * (2 * NE) + k];
            g_WwhhT[idx] = Ww_hh[(g * NH + u) * NH + k];
        }
        // char weights: [k=256][c=1024]
        if (idx < 262144) {
            int c = idx & 1023, k = idx >> 10;      // k in [0,256)
            int u = c >> 2, g = c & 3;
            g_WcihT[idx] = Wc_ih[(g * NE + u) * NE + k];
            g_WchhT[idx] = Wc_hh[(g * NE + u) * NE + k];
        }
        if (idx < 2048) {
            int u = idx >> 2, g = idx & 3;
            g_bwp[idx] = bw[g * NH + u];
        }
        if (idx < 1024) {
            int u = idx >> 2, g = idx & 3;
            g_bcp[idx] = bc[g * NE + u];
        }
        if (idx < 4) g_bar4[idx] = 0u;
    }
}

// ---------------- char LSTM step (FFMA2 inner loop; R8/R10-verified) ----------------
__global__ __launch_bounds__(256, 2)
void char_step_kernel(const int* __restrict__ char_idx,
                      const float* __restrict__ char_emb, int t)
{
    __shared__ float Xs[16][68];     // [k][token], padded
    __shared__ float Ws[16][260];    // [k][col],   padded
    __shared__ int   idxs[64];

    const int tid = threadIdx.x;
    const int tx = tid & 63;
    const int ty = tid >> 6;
    const int tok0 = blockIdx.x * 64;
    const int c0 = blockIdx.y * 256;

    float* hnew        = (t & 1) ? g_HcB : g_HcA;
    const float* hprev = (t & 1) ? g_HcA : g_HcB;

    unsigned long long acc2[8][4];   // [row-pair][col], packed f32x2
#pragma unroll
    for (int rp = 0; rp < 8; rp++) {
        acc2[rp][0] = 0ull; acc2[rp][1] = 0ull; acc2[rp][2] = 0ull; acc2[rp][3] = 0ull;
    }

    if (tid < 64) idxs[tid] = char_idx[(tok0 + tid) * NC + t];
    __syncthreads();

    const int npass = (t == 0) ? 1 : 2;
    for (int pass = 0; pass < npass; pass++) {
        const float* W = pass ? g_WchhT : g_WcihT;
        for (int kc = 0; kc < 16; kc++) {
            const int k0 = kc * 16;
            {
                int tok = tid >> 2, kq = tid & 3;
                float4 v;
                if (pass == 0)
                    v = *(const float4*)&char_emb[idxs[tok] * NE + k0 + kq * 4];
                else
                    v = *(const float4*)&hprev[(tok0 + tok) * NE + k0 + kq * 4];
                Xs[kq * 4 + 0][tok] = v.x;
                Xs[kq * 4 + 1][tok] = v.y;
                Xs[kq * 4 + 2][tok] = v.z;
                Xs[kq * 4 + 3][tok] = v.w;
            }
#pragma unroll
            for (int j = 0; j < 4; j++) {
                int f = tid + j * 256;
                int kk = f >> 6, cq = f & 63;
                *(float4*)&Ws[kk][cq * 4] =
                    *(const float4*)&W[(k0 + kk) * 1024 + c0 + cq * 4];
            }
            __syncthreads();
#pragma unroll
            for (int k = 0; k < 16; k++) {
                float4 b = *(float4*)&Ws[k][tx * 4];
                unsigned long long bs0 = splat2(b.x);
                unsigned long long bs1 = splat2(b.y);
                unsigned long long bs2 = splat2(b.z);
                unsigned long long bs3 = splat2(b.w);
                ulonglong2 A0 = *(const ulonglong2*)&Xs[k][ty * 16 + 0];
                ulonglong2 A1 = *(const ulonglong2*)&Xs[k][ty * 16 + 4];
                ulonglong2 A2 = *(const ulonglong2*)&Xs[k][ty * 16 + 8];
                ulonglong2 A3 = *(const ulonglong2*)&Xs[k][ty * 16 + 12];
                unsigned long long ap[8] = {A0.x, A0.y, A1.x, A1.y, A2.x, A2.y, A3.x, A3.y};
#pragma unroll
                for (int rp = 0; rp < 8; rp++) {
                    ffma2(acc2[rp][0], ap[rp], bs0);
                    ffma2(acc2[rp][1], ap[rp], bs1);
                    ffma2(acc2[rp][2], ap[rp], bs2);
                    ffma2(acc2[rp][3], ap[rp], bs3);
                }
            }
            __syncthreads();
        }
    }

    const int u = (c0 >> 2) + tx;                  // global unit 0..255
    float4 bias = *(const float4*)&g_bcp[c0 + tx * 4];
#pragma unroll
    for (int rp = 0; rp < 8; rp++) {
        float2 gi2 = unpack2(acc2[rp][0]);
        float2 gf2 = unpack2(acc2[rp][1]);
        float2 gg2 = unpack2(acc2[rp][2]);
        float2 go2 = unpack2(acc2[rp][3]);
#pragma unroll
        for (int hh = 0; hh < 2; hh++) {
            int tok = tok0 + ty * 16 + rp * 2 + hh;
            float gi = (hh ? gi2.y : gi2.x) + bias.x;
            float gf = (hh ? gf2.y : gf2.x) + bias.y;
            float gg = (hh ? gg2.y : gg2.x) + bias.z;
            float go = (hh ? go2.y : go2.x) + bias.w;
            float cp = (t == 0) ? 0.f : g_Cc[tok * NE + u];
            float cn = sigm_(gf) * cp + sigm_(gi) * tanh_(gg);
            float h  = sigm_(go) * tanh_(cn);
            g_Cc[tok * NE + u] = cn;
            hnew[tok * NE + u] = h;
        }
    }
}

// ---------------- word-input GEMM: XW = [we ; char_feat] @ WwihT + bw (FFMA2) -------
__global__ __launch_bounds__(256, 2)
void xw_kernel(const int* __restrict__ word_idx, const float* __restrict__ word_emb)
{
    __shared__ float Xs[16][68];
    __shared__ float Ws[16][260];
    __shared__ int   idxs[64];

    const int tid = threadIdx.x;
    const int tx = tid & 63;
    const int ty = tid >> 6;
    const int tok0 = blockIdx.x * 64;
    const int c0 = blockIdx.y * 256;

    unsigned long long acc2[8][4];
#pragma unroll
    for (int rp = 0; rp < 8; rp++) {
        acc2[rp][0] = 0ull; acc2[rp][1] = 0ull; acc2[rp][2] = 0ull; acc2[rp][3] = 0ull;
    }

    if (tid < 64) idxs[tid] = word_idx[tok0 + tid];
    __syncthreads();

    for (int kc = 0; kc < 32; kc++) {
        const int k0 = kc * 16;
        {
            int tok = tid >> 2, kq = tid & 3;
            float4 v;
            if (kc < 16)
                v = *(const float4*)&word_emb[(size_t)idxs[tok] * NE + k0 + kq * 4];
            else
                v = *(const float4*)&g_HcB[(tok0 + tok) * NE + (k0 - NE) + kq * 4];
            Xs[kq * 4 + 0][tok] = v.x;
            Xs[kq * 4 + 1][tok] = v.y;
            Xs[kq * 4 + 2][tok] = v.z;
            Xs[kq * 4 + 3][tok] = v.w;
        }
#pragma unroll
        for (int j = 0; j < 4; j++) {
            int f = tid + j * 256;
            int kk = f >> 6, cq = f & 63;
            *(float4*)&Ws[kk][cq * 4] =
                *(const float4*)&g_WwihT[(k0 + kk) * 2048 + c0 + cq * 4];
        }
        __syncthreads();
#pragma unroll
        for (int k = 0; k < 16; k++) {
            float4 b = *(float4*)&Ws[k][tx * 4];
            unsigned long long bs0 = splat2(b.x);
            unsigned long long bs1 = splat2(b.y);
            unsigned long long bs2 = splat2(b.z);
            unsigned long long bs3 = splat2(b.w);
            ulonglong2 A0 = *(const ulonglong2*)&Xs[k][ty * 16 + 0];
            ulonglong2 A1 = *(const ulonglong2*)&Xs[k][ty * 16 + 4];
            ulonglong2 A2 = *(const ulonglong2*)&Xs[k][ty * 16 + 8];
            ulonglong2 A3 = *(const ulonglong2*)&Xs[k][ty * 16 + 12];
            unsigned long long ap[8] = {A0.x, A0.y, A1.x, A1.y, A2.x, A2.y, A3.x, A3.y};
#pragma unroll
            for (int rp = 0; rp < 8; rp++) {
                ffma2(acc2[rp][0], ap[rp], bs0);
                ffma2(acc2[rp][1], ap[rp], bs1);
                ffma2(acc2[rp][2], ap[rp], bs2);
                ffma2(acc2[rp][3], ap[rp], bs3);
            }
        }
        __syncthreads();
    }

    float4 bias = *(const float4*)&g_bwp[c0 + tx * 4];
#pragma unroll
    for (int rp = 0; rp < 8; rp++) {
        float2 o0 = unpack2(acc2[rp][0]);
        float2 o1 = unpack2(acc2[rp][1]);
        float2 o2 = unpack2(acc2[rp][2]);
        float2 o3 = unpack2(acc2[rp][3]);
#pragma unroll
        for (int hh = 0; hh < 2; hh++) {
            int tok = tok0 + ty * 16 + rp * 2 + hh;
            float4 o;
            o.x = (hh ? o0.y : o0.x) + bias.x;
            o.y = (hh ? o1.y : o1.x) + bias.y;
            o.z = (hh ? o2.y : o2.x) + bias.z;
            o.w = (hh ? o3.y : o3.x) + bias.w;
            *(float4*)&g_XW[(size_t)tok * 2048 + c0 + tx * 4] = o;
        }
    }
}

// ---------------- word LSTM: subgrid decomposition ----------------
// 128 CTAs = 4 independent subgrids x 32 CTAs. Subgrid `sub` owns batches
// [sub*8, sub*8+8); CTA cg_ within subgrid owns gate-cols [cg_*64, cg_*64+64)
// (16 units). Weights smem-resident; h exchanged through L2 (__stcg/__ldcg);
// per-subgrid monotonic counter barrier (residency guaranteed by cooperative
// launch + host occupancy precheck).
//
// smem: ws [512][68] (64 cols + pad)  -> 139264 B
//       hs [8][516]  h_prev, b-major  ->  16512 B
//       ps [128][4]  k-half partials  ->   2048 B
#define WWS_STRIDE 68
#define WWS_FLOATS (512 * WWS_STRIDE)
#define WHS_STRIDE 516
#define WHS_FLOATS (8 * WHS_STRIDE)
#define WPS_FLOATS (128 * 4)
#define WORD_SMEM_BYTES ((WWS_FLOATS + WHS_FLOATS + WPS_FLOATS) * 4)
#define WORD_THREADS 256

__device__ __forceinline__ void word_fill_ws(float* ws, int c0, int tid)
{
    for (int idx = tid; idx < 512 * 64; idx += WORD_THREADS) {
        int k = idx >> 6, j = idx & 63;
        ws[k * WWS_STRIDE + j] = g_WwhhT[k * 2048 + c0 + j];
    }
}

// Fill hs[b_l][k] for 8 batches from g_Hsave(t-1); L2-coherent loads.
__device__ __forceinline__ void word_fill_hs(float* hs, int t, int b0, int tid)
{
    if (t == 0) {
        for (int i = tid; i < WHS_FLOATS; i += WORD_THREADS) hs[i] = 0.f;
    } else {
#pragma unroll 4
        for (int i = tid; i < 1024; i += WORD_THREADS) {   // 1024 float4 = 8b x 128
            int bb = i >> 7, k4 = i & 127;
            float4 v = __ldcg((const float4*)&g_Hsave[
                (size_t)(((b0 + bb) << 10) + (t - 1)) * NH + k4 * 4]);
            *(float4*)&hs[bb * WHS_STRIDE + k4 * 4] = v;
        }
    }
}

// Half-range inner product: 4 gate-cols of local unit u_l over k in [k0,k0+256).
__device__ __forceinline__ float4 word_dot_half(const float* hrow, const float* ws,
                                                int u_l, int k0)
{
    float4 acc = make_float4(0.f, 0.f, 0.f, 0.f);
#pragma unroll 8
    for (int k = k0; k < k0 + 256; k += 4) {
        float4 h4 = *(const float4*)&hrow[k];
        float4 w0 = *(const float4*)&ws[(k + 0) * WWS_STRIDE + u_l * 4];
        float4 w1 = *(const float4*)&ws[(k + 1) * WWS_STRIDE + u_l * 4];
        float4 w2 = *(const float4*)&ws[(k + 2) * WWS_STRIDE + u_l * 4];
        float4 w3 = *(const float4*)&ws[(k + 3) * WWS_STRIDE + u_l * 4];
        acc.x += h4.x * w0.x; acc.y += h4.x * w0.y; acc.z += h4.x * w0.z; acc.w += h4.x * w0.w;
        acc.x += h4.y * w1.x; acc.y += h4.y * w1.y; acc.z += h4.y * w1.z; acc.w += h4.y * w1.w;
        acc.x += h4.z * w2.x; acc.y += h4.z * w2.y; acc.z += h4.z * w2.z; acc.w += h4.z * w2.w;
        acc.x += h4.w * w3.x; acc.y += h4.w * w3.y; acc.z += h4.w * w3.z; acc.w += h4.w * w3.w;
    }
    return acc;
}

// Shared per-step body. tid: khalf = tid>>7, r = tid&127, b_l = r>>4, u_l = r&15.
// All __syncthreads unconditional. Returns updated c (valid for khalf==0 threads).
__device__ __forceinline__ float word_step_body(float* ws, float* hs, float* ps,
                                                int t, int tid, int c0, int b0, float c)
{
    const int khalf = tid >> 7;
    const int r   = tid & 127;
    const int b_l = r >> 4;
    const int u_l = r & 15;
    const int ug  = (c0 >> 2) + u_l;               // global unit 0..511

    word_fill_hs(hs, t, b0, tid);
    __syncthreads();

    float4 acc = word_dot_half(&hs[b_l * WHS_STRIDE], ws, u_l, khalf * 256);

    if (khalf == 1) *(float4*)&ps[r * 4] = acc;
    __syncthreads();

    if (khalf == 0) {
        float4 p = *(const float4*)&ps[r * 4];
        const size_t n = (size_t)((b0 + b_l) << 10) + t;
        float4 a = *(const float4*)&g_XW[n * 2048 + c0 + u_l * 4];
        float gi = acc.x + p.x + a.x;     // bias already folded into XW
        float gf = acc.y + p.y + a.y;
        float gg = acc.z + p.z + a.z;
        float go = acc.w + p.w + a.w;
        c = sigm_(gf) * c + sigm_(gi) * tanh_(gg);
        float h = sigm_(go) * tanh_(c);
        __stcg(&g_Hsave[n * NH + ug], h);          // L2-coherent publish
    }
    return c;
}

// ---------------- word LSTM, cooperative (1 launch, per-subgrid barriers) ----------
__global__ __launch_bounds__(WORD_THREADS, 1)
void word_coop_kernel(int /*dummy*/)
{
    extern __shared__ float sm[];
    float* ws = sm;
    float* hs = sm + WWS_FLOATS;
    float* ps = hs + WHS_FLOATS;

    const int tid = threadIdx.x;
    const int sub = blockIdx.x >> 5;               // subgrid 0..3
    const int cg_ = blockIdx.x & 31;               // CTA within subgrid
    const int c0  = cg_ * 64;
    const int b0  = sub * 8;

    word_fill_ws(ws, c0, tid);

    float c = 0.f;
    for (int t = 0; t < NS; t++) {
        c = word_step_body(ws, hs, ps, t, tid, c0, b0, c);

        // per-subgrid barrier: release (fence+add), acquire (spin+fence)
        __threadfence();
        __syncthreads();
        if (tid == 0) {
            atomicAdd(&g_bar4[sub], 1u);
            const unsigned target = (unsigned)(t + 1) * 32u;
            while (*(volatile unsigned int*)&g_bar4[sub] < target) __nanosleep(32);
            __threadfence();
        }
        __syncthreads();
    }
}

// ---------------- word LSTM fallback: one launch per step ----------------
__global__ __launch_bounds__(WORD_THREADS, 1)
void word_step_kernel(int t)
{
    extern __shared__ float sm[];
    float* ws = sm;
    float* hs = sm + WWS_FLOATS;
    float* ps = hs + WHS_FLOATS;

    const int tid = threadIdx.x;
    const int sub = blockIdx.x >> 5;
    const int cg_ = blockIdx.x & 31;
    const int c0  = cg_ * 64;
    const int b0  = sub * 8;
    const int khalf = tid >> 7;
    const int r   = tid & 127;
    const int b_l = r >> 4;
    const int u_l = r & 15;
    const int ug  = (c0 >> 2) + u_l;

    word_fill_ws(ws, c0, tid);

    float c = (t == 0 || khalf) ? 0.f : g_Cw[(b0 + b_l) * NH + ug];
    c = word_step_body(ws, hs, ps, t, tid, c0, b0, c);
    if (khalf == 0) g_Cw[(b0 + b_l) * NH + ug] = c;
}

// ---------------- logits + log_softmax ----------------
__global__ __launch_bounds__(256, 1)
void logits_kernel(const float* __restrict__ Wt, const float* __restrict__ bt,
                   float* __restrict__ out)
{
    extern __shared__ float sm[];
    float* Wts = sm;               // [512][65]
    float* hs  = sm + 512 * 65;    // [4][512]
    __shared__ float sl[4][64];

    const int tid = threadIdx.x;
    for (int idx = tid; idx < 512 * 64; idx += 256) {
        int tg = idx >> 9, k = idx & 511;
        Wts[k * 65 + tg] = (tg < NT) ? Wt[tg * NH + k] : 0.f;
    }
    const int tokl = tid >> 6, tag = tid & 63;
    const int wid = tid >> 5, lane = tid & 31;
    float btv = (tag < NT) ? bt[tag] : 0.f;

    for (int tb = blockIdx.x; tb < NTOK / 4; tb += gridDim.x) {
        __syncthreads();
        for (int idx = tid; idx < 2048; idx += 256) {
            int tk = idx >> 9, k = idx & 511;
            hs[tk * 512 + k] = g_Hsave[(size_t)(tb * 4 + tk) * NH + k];
        }
        __syncthreads();
        float acc = 0.f;
#pragma unroll 8
        for (int k = 0; k < 512; k++)
            acc += hs[tokl * 512 + k] * Wts[k * 65 + tag];
        sl[tokl][tag] = (tag < NT) ? (acc + btv) : -1e30f;
        __syncthreads();
        if (wid < 4) {
            float l0 = sl[wid][lane], l1 = sl[wid][lane + 32];
            float m = fmaxf(l0, l1);
#pragma unroll
            for (int o = 16; o; o >>= 1) m = fmaxf(m, __shfl_xor_sync(0xffffffffu, m, o));
            float s = __expf(l0 - m) + __expf(l1 - m);
#pragma unroll
            for (int o = 16; o; o >>= 1) s += __shfl_xor_sync(0xffffffffu, s, o);
            float lse = m + __logf(s);
            int n = tb * 4 + wid;
            for (int j = lane; j < NT; j += 32)
                out[(size_t)n * NT + j] = sl[wid][j] - lse;
        }
    }
}

// ---------------- launch ----------------
extern "C" void kernel_launch(void* const* d_in, const int* in_sizes, int n_in,
                              void* d_out, int out_size)
{
    const int*   char_idx = (const int*)d_in[0];
    const int*   word_idx = (const int*)d_in[1];
    const float* char_emb = (const float*)d_in[2];
    const float* word_emb = (const float*)d_in[3];
    const float* Wc_ih    = (const float*)d_in[4];
    const float* Wc_hh    = (const float*)d_in[5];
    const float* bc       = (const float*)d_in[6];
    const float* Ww_ih    = (const float*)d_in[7];
    const float* Ww_hh    = (const float*)d_in[8];
    const float* bw       = (const float*)d_in[9];
    const float* Wt       = (const float*)d_in[10];
    const float* bt       = (const float*)d_in[11];
    float* out = (float*)d_out;

    const int word_smem   = WORD_SMEM_BYTES;             // 157824 B
    const int logits_smem = (512 * 65 + 4 * 512) * 4;    // 141312 B
    cudaFuncSetAttribute(word_coop_kernel,
                         cudaFuncAttributeMaxDynamicSharedMemorySize, word_smem);
    cudaFuncSetAttribute(word_step_kernel,
                         cudaFuncAttributeMaxDynamicSharedMemorySize, word_smem);
    cudaFuncSetAttribute(logits_kernel,
                         cudaFuncAttributeMaxDynamicSharedMemorySize, logits_smem);

    // Deterministic host-side decision: cooperative path only if the device
    // guarantees 128 co-resident CTAs (pure queries, capture-legal).
    int dev = 0;
    cudaGetDevice(&dev);
    int numSM = 0, coopAttr = 0, perSM = 0;
    cudaDeviceGetAttribute(&numSM, cudaDevAttrMultiProcessorCount, dev);
    cudaDeviceGetAttribute(&coopAttr, cudaDevAttrCooperativeLaunch, dev);
    cudaOccupancyMaxActiveBlocksPerMultiprocessor(&perSM, word_coop_kernel,
                                                  WORD_THREADS, word_smem);
    const bool coop_ok = (coopAttr != 0) && (perSM >= 1) && (numSM >= 128);

    prep_all_kernel<<<4096, 256>>>(Wc_ih, Wc_hh, bc, Ww_ih, Ww_hh, bw);

    for (int t = 0; t < NC; t++)
        char_step_kernel<<<dim3(NTOK / 64, 4), 256>>>(char_idx, char_emb, t);

    xw_kernel<<<dim3(NTOK / 64, 8), 256>>>(word_idx, word_emb);

    if (coop_ok) {
        int dummy = 0;
        void* kargs[] = { &dummy };
        cudaLaunchCooperativeKernel((void*)word_coop_kernel,
                                    dim3(128), dim3(WORD_THREADS),
                                    kargs, (size_t)word_smem, (cudaStream_t)0);
    } else {
        for (int t = 0; t < NS; t++)
            word_step_kernel<<<128, WORD_THREADS, word_smem>>>(t);
    }

    logits_kernel<<<148, 256, logits_smem>>>(Wt, bt, out);
}

// round 12
// speedup vs baseline: 2.2054x; 1.1953x over previous
#include <cuda_runtime.h>
#include <cuda_bf16.h>
#include <cooperative_groups.h>
#include <stdint.h>

namespace cg = cooperative_groups;

// Problem dims
#define NB 32
#define NS 1024
#define NC 12
#define NE 256
#define NH 512
#define NT 50
#define NTOK (NB*NS)          // 32768

// ---------------- device scratch (allocation-free) ----------------
__device__ float g_WcihT[NE * 4 * NE];            // [k=256][1024] col 4u+g <- row g*256+u
__device__ float g_WchhT[NE * 4 * NE];
__device__ float g_bcp[4 * NE];
__device__ float g_WwihT[2 * NE * 4 * NH];        // [k=512][2048]
__device__ float g_WwhhT[NH * 4 * NH];            // [k=512][2048]
__device__ float g_bwp[4 * NH];

__device__ float g_HcA[NTOK * NE];                // char h ping
__device__ float g_HcB[NTOK * NE];                // char h pong (holds final char_feat)
__device__ float g_Cc [NTOK * NE];                // char c state
__device__ float g_XW [(size_t)NTOK * 4 * NH];    // word-input preacts + bias, [n][2048]
__device__ float g_Hsave[(size_t)NTOK * NH];      // word hidden trace [n][512]
__device__ float g_Cw [NB * NH];                  // word c state (fallback path only)
__device__ unsigned int g_bar4[4];                // per-subgrid monotonic barrier counters

// ---------------- math helpers ----------------
__device__ __forceinline__ float sigm_(float x) {
    return __fdividef(1.f, 1.f + __expf(-x));
}
__device__ __forceinline__ float tanh_(float x) {
    return __fdividef(2.f, 1.f + __expf(-2.f * x)) - 1.f;
}

// ---------------- packed f32x2 helpers (sm_100+) ----------------
__device__ __forceinline__ unsigned long long splat2(float x) {
    unsigned long long r;
    asm("mov.b64 %0, {%1, %1};" : "=l"(r) : "f"(x));
    return r;
}
__device__ __forceinline__ void ffma2(unsigned long long& d,
                                      unsigned long long a, unsigned long long b) {
    asm("fma.rn.f32x2 %0, %1, %2, %0;" : "+l"(d) : "l"(a), "l"(b));
}
__device__ __forceinline__ float2 unpack2(unsigned long long v) {
    float2 f;
    asm("mov.b64 {%0, %1}, %2;" : "=f"(f.x), "=f"(f.y) : "l"(v));
    return f;
}

// ---------------- prep: permute/transpose weights, zero barriers ----------------
__global__ void prep_all_kernel(const float* __restrict__ Wc_ih,
                                const float* __restrict__ Wc_hh,
                                const float* __restrict__ bc,
                                const float* __restrict__ Ww_ih,
                                const float* __restrict__ Ww_hh,
                                const float* __restrict__ bw)
{
    const int stride = gridDim.x * blockDim.x;
    for (int idx = blockIdx.x * blockDim.x + threadIdx.x; idx < 1048576; idx += stride) {
        // word weights: [k=512][c=2048], WT[k*2048 + (4u+g)] = W[(g*512+u)*Kdim + k]
        {
            int c = idx & 2047, k = idx >> 11;      // k in [0,512)
            int u = c >> 2, g = c & 3;
            g_WwihT[idx] = Ww_ih[(g * NH + u) * (2 * NE) + k];
            g_WwhhT[idx] = Ww_hh[(g * NH + u) * NH + k];
        }
        // char weights: [k=256][c=1024]
        if (idx < 262144) {
            int c = idx & 1023, k = idx >> 10;      // k in [0,256)
            int u = c >> 2, g = c & 3;
            g_WcihT[idx] = Wc_ih[(g * NE + u) * NE + k];
            g_WchhT[idx] = Wc_hh[(g * NE + u) * NE + k];
        }
        if (idx < 2048) {
            int u = idx >> 2, g = idx & 3;
            g_bwp[idx] = bw[g * NH + u];
        }
        if (idx < 1024) {
            int u = idx >> 2, g = idx & 3;
            g_bcp[idx] = bc[g * NE + u];
        }
        if (idx < 4) g_bar4[idx] = 0u;
    }
}

// ---------------- char LSTM step (FFMA2 inner loop; R8/R10-verified) ----------------
__global__ __launch_bounds__(256, 2)
void char_step_kernel(const int* __restrict__ char_idx,
                      const float* __restrict__ char_emb, int t)
{
    __shared__ float Xs[16][68];     // [k][token], padded
    __shared__ float Ws[16][260];    // [k][col],   padded
    __shared__ int   idxs[64];

    const int tid = threadIdx.x;
    const int tx = tid & 63;
    const int ty = tid >> 6;
    const int tok0 = blockIdx.x * 64;
    const int c0 = blockIdx.y * 256;

    float* hnew        = (t & 1) ? g_HcB : g_HcA;
    const float* hprev = (t & 1) ? g_HcA : g_HcB;

    unsigned long long acc2[8][4];   // [row-pair][col], packed f32x2
#pragma unroll
    for (int rp = 0; rp < 8; rp++) {
        acc2[rp][0] = 0ull; acc2[rp][1] = 0ull; acc2[rp][2] = 0ull; acc2[rp][3] = 0ull;
    }

    if (tid < 64) idxs[tid] = char_idx[(tok0 + tid) * NC + t];
    __syncthreads();

    const int npass = (t == 0) ? 1 : 2;
    for (int pass = 0; pass < npass; pass++) {
        const float* W = pass ? g_WchhT : g_WcihT;
        for (int kc = 0; kc < 16; kc++) {
            const int k0 = kc * 16;
            {
                int tok = tid >> 2, kq = tid & 3;
                float4 v;
                if (pass == 0)
                    v = *(const float4*)&char_emb[idxs[tok] * NE + k0 + kq * 4];
                else
                    v = *(const float4*)&hprev[(tok0 + tok) * NE + k0 + kq * 4];
                Xs[kq * 4 + 0][tok] = v.x;
                Xs[kq * 4 + 1][tok] = v.y;
                Xs[kq * 4 + 2][tok] = v.z;
                Xs[kq * 4 + 3][tok] = v.w;
            }
#pragma unroll
            for (int j = 0; j < 4; j++) {
                int f = tid + j * 256;
                int kk = f >> 6, cq = f & 63;
                *(float4*)&Ws[kk][cq * 4] =
                    *(const float4*)&W[(k0 + kk) * 1024 + c0 + cq * 4];
            }
            __syncthreads();
#pragma unroll
            for (int k = 0; k < 16; k++) {
                float4 b = *(float4*)&Ws[k][tx * 4];
                unsigned long long bs0 = splat2(b.x);
                unsigned long long bs1 = splat2(b.y);
                unsigned long long bs2 = splat2(b.z);
                unsigned long long bs3 = splat2(b.w);
                ulonglong2 A0 = *(const ulonglong2*)&Xs[k][ty * 16 + 0];
                ulonglong2 A1 = *(const ulonglong2*)&Xs[k][ty * 16 + 4];
                ulonglong2 A2 = *(const ulonglong2*)&Xs[k][ty * 16 + 8];
                ulonglong2 A3 = *(const ulonglong2*)&Xs[k][ty * 16 + 12];
                unsigned long long ap[8] = {A0.x, A0.y, A1.x, A1.y, A2.x, A2.y, A3.x, A3.y};
#pragma unroll
                for (int rp = 0; rp < 8; rp++) {
                    ffma2(acc2[rp][0], ap[rp], bs0);
                    ffma2(acc2[rp][1], ap[rp], bs1);
                    ffma2(acc2[rp][2], ap[rp], bs2);
                    ffma2(acc2[rp][3], ap[rp], bs3);
                }
            }
            __syncthreads();
        }
    }

    const int u = (c0 >> 2) + tx;                  // global unit 0..255
    float4 bias = *(const float4*)&g_bcp[c0 + tx * 4];
#pragma unroll
    for (int rp = 0; rp < 8; rp++) {
        float2 gi2 = unpack2(acc2[rp][0]);
        float2 gf2 = unpack2(acc2[rp][1]);
        float2 gg2 = unpack2(acc2[rp][2]);
        float2 go2 = unpack2(acc2[rp][3]);
#pragma unroll
        for (int hh = 0; hh < 2; hh++) {
            int tok = tok0 + ty * 16 + rp * 2 + hh;
            float gi = (hh ? gi2.y : gi2.x) + bias.x;
            float gf = (hh ? gf2.y : gf2.x) + bias.y;
            float gg = (hh ? gg2.y : gg2.x) + bias.z;
            float go = (hh ? go2.y : go2.x) + bias.w;
            float cp = (t == 0) ? 0.f : g_Cc[tok * NE + u];
            float cn = sigm_(gf) * cp + sigm_(gi) * tanh_(gg);
            float h  = sigm_(go) * tanh_(cn);
            g_Cc[tok * NE + u] = cn;
            hnew[tok * NE + u] = h;
        }
    }
}

// ---------------- word-input GEMM: XW = [we ; char_feat] @ WwihT + bw (FFMA2) -------
__global__ __launch_bounds__(256, 2)
void xw_kernel(const int* __restrict__ word_idx, const float* __restrict__ word_emb)
{
    __shared__ float Xs[16][68];
    __shared__ float Ws[16][260];
    __shared__ int   idxs[64];

    const int tid = threadIdx.x;
    const int tx = tid & 63;
    const int ty = tid >> 6;
    const int tok0 = blockIdx.x * 64;
    const int c0 = blockIdx.y * 256;

    unsigned long long acc2[8][4];
#pragma unroll
    for (int rp = 0; rp < 8; rp++) {
        acc2[rp][0] = 0ull; acc2[rp][1] = 0ull; acc2[rp][2] = 0ull; acc2[rp][3] = 0ull;
    }

    if (tid < 64) idxs[tid] = word_idx[tok0 + tid];
    __syncthreads();

    for (int kc = 0; kc < 32; kc++) {
        const int k0 = kc * 16;
        {
            int tok = tid >> 2, kq = tid & 3;
            float4 v;
            if (kc < 16)
                v = *(const float4*)&word_emb[(size_t)idxs[tok] * NE + k0 + kq * 4];
            else
                v = *(const float4*)&g_HcB[(tok0 + tok) * NE + (k0 - NE) + kq * 4];
            Xs[kq * 4 + 0][tok] = v.x;
            Xs[kq * 4 + 1][tok] = v.y;
            Xs[kq * 4 + 2][tok] = v.z;
            Xs[kq * 4 + 3][tok] = v.w;
        }
#pragma unroll
        for (int j = 0; j < 4; j++) {
            int f = tid + j * 256;
            int kk = f >> 6, cq = f & 63;
            *(float4*)&Ws[kk][cq * 4] =
                *(const float4*)&g_WwihT[(k0 + kk) * 2048 + c0 + cq * 4];
        }
        __syncthreads();
#pragma unroll
        for (int k = 0; k < 16; k++) {
            float4 b = *(float4*)&Ws[k][tx * 4];
            unsigned long long bs0 = splat2(b.x);
            unsigned long long bs1 = splat2(b.y);
            unsigned long long bs2 = splat2(b.z);
            unsigned long long bs3 = splat2(b.w);
            ulonglong2 A0 = *(const ulonglong2*)&Xs[k][ty * 16 + 0];
            ulonglong2 A1 = *(const ulonglong2*)&Xs[k][ty * 16 + 4];
            ulonglong2 A2 = *(const ulonglong2*)&Xs[k][ty * 16 + 8];
            ulonglong2 A3 = *(const ulonglong2*)&Xs[k][ty * 16 + 12];
            unsigned long long ap[8] = {A0.x, A0.y, A1.x, A1.y, A2.x, A2.y, A3.x, A3.y};
#pragma unroll
            for (int rp = 0; rp < 8; rp++) {
                ffma2(acc2[rp][0], ap[rp], bs0);
                ffma2(acc2[rp][1], ap[rp], bs1);
                ffma2(acc2[rp][2], ap[rp], bs2);
                ffma2(acc2[rp][3], ap[rp], bs3);
            }
        }
        __syncthreads();
    }

    float4 bias = *(const float4*)&g_bwp[c0 + tx * 4];
#pragma unroll
    for (int rp = 0; rp < 8; rp++) {
        float2 o0 = unpack2(acc2[rp][0]);
        float2 o1 = unpack2(acc2[rp][1]);
        float2 o2 = unpack2(acc2[rp][2]);
        float2 o3 = unpack2(acc2[rp][3]);
#pragma unroll
        for (int hh = 0; hh < 2; hh++) {
            int tok = tok0 + ty * 16 + rp * 2 + hh;
            float4 o;
            o.x = (hh ? o0.y : o0.x) + bias.x;
            o.y = (hh ? o1.y : o1.x) + bias.y;
            o.z = (hh ? o2.y : o2.x) + bias.z;
            o.w = (hh ? o3.y : o3.x) + bias.w;
            *(float4*)&g_XW[(size_t)tok * 2048 + c0 + tx * 4] = o;
        }
    }
}

// ---------------- word LSTM: subgrid decomposition + high-reuse dot ----------------
// 128 CTAs = 4 independent subgrids x 32 CTAs. Subgrid `sub` owns batches
// [sub*8, +8); CTA cg_ owns gate-cols [cg_*64, +64) (16 units).
// Thread (ks, pos): ks = tid>>5 (k-slice of 64), pos = tid&31: u_l = pos>>1 (unit),
// bq = pos&1 (batch quad). Each thread: 4 cols x 4 batches x 64 k
// -> 8 LDS.128 per 64 MACs (2.5x fewer LDS than R11). 8-way k-partials reduced
// through smem; 128 threads do the reduction + pointwise (c-state in their regs).
//
// smem: ws [512][68]            -> 139264 B
//       hs [8][516]  b-major    ->  16512 B
//       ps [8][32][20]          ->  20480 B
#define WWS_STRIDE 68
#define WWS_FLOATS (512 * WWS_STRIDE)
#define WHS_STRIDE 516
#define WHS_FLOATS (8 * WHS_STRIDE)
#define WPS_FLOATS (8 * 32 * 20)
#define WORD_SMEM_BYTES ((WWS_FLOATS + WHS_FLOATS + WPS_FLOATS) * 4)
#define WORD_THREADS 256

__device__ __forceinline__ void word_fill_ws(float* ws, int c0, int tid)
{
    for (int idx = tid; idx < 512 * 64; idx += WORD_THREADS) {
        int k = idx >> 6, j = idx & 63;
        ws[k * WWS_STRIDE + j] = g_WwhhT[k * 2048 + c0 + j];
    }
}

// Fill hs[b_l][k] for 8 batches from g_Hsave(t-1); L2-coherent loads.
__device__ __forceinline__ void word_fill_hs(float* hs, int t, int b0, int tid)
{
    if (t == 0) {
        for (int i = tid; i < WHS_FLOATS; i += WORD_THREADS) hs[i] = 0.f;
    } else {
#pragma unroll 4
        for (int i = tid; i < 1024; i += WORD_THREADS) {   // 1024 float4 = 8b x 128
            int bb = i >> 7, k4 = i & 127;
            float4 v = __ldcg((const float4*)&g_Hsave[
                (size_t)(((b0 + bb) << 10) + (t - 1)) * NH + k4 * 4]);
            *(float4*)&hs[bb * WHS_STRIDE + k4 * 4] = v;
        }
    }
}

// Shared per-step body. Returns updated c (meaningful for tid<128 cell owners).
// All __syncthreads unconditional (uniform control flow).
__device__ __forceinline__ float word_step_body(float* ws, float* hs, float* ps,
                                                int t, int tid, int c0, int b0, float c)
{
    const int ks  = tid >> 5;          // k-slice 0..7
    const int pos = tid & 31;
    const int u_l = pos >> 1;          // unit 0..15
    const int bq  = pos & 1;           // batch quad 0..1
    const int k0  = ks * 64;

    word_fill_hs(hs, t, b0, tid);
    __syncthreads();

    float4 acc[4];
    acc[0] = make_float4(0.f, 0.f, 0.f, 0.f);
    acc[1] = make_float4(0.f, 0.f, 0.f, 0.f);
    acc[2] = make_float4(0.f, 0.f, 0.f, 0.f);
    acc[3] = make_float4(0.f, 0.f, 0.f, 0.f);

    const float* hbase = &hs[(bq * 4) * WHS_STRIDE];
#pragma unroll 4
    for (int k = k0; k < k0 + 64; k += 4) {
        float4 w0 = *(const float4*)&ws[(k + 0) * WWS_STRIDE + u_l * 4];
        float4 w1 = *(const float4*)&ws[(k + 1) * WWS_STRIDE + u_l * 4];
        float4 w2 = *(const float4*)&ws[(k + 2) * WWS_STRIDE + u_l * 4];
        float4 w3 = *(const float4*)&ws[(k + 3) * WWS_STRIDE + u_l * 4];
#pragma unroll
        for (int j = 0; j < 4; j++) {
            float4 hb = *(const float4*)&hbase[j * WHS_STRIDE + k];
            acc[j].x += hb.x * w0.x; acc[j].y += hb.x * w0.y;
            acc[j].z += hb.x * w0.z; acc[j].w += hb.x * w0.w;
            acc[j].x += hb.y * w1.x; acc[j].y += hb.y * w1.y;
            acc[j].z += hb.y * w1.z; acc[j].w += hb.y * w1.w;
            acc[j].x += hb.z * w2.x; acc[j].y += hb.z * w2.y;
            acc[j].z += hb.z * w2.z; acc[j].w += hb.z * w2.w;
            acc[j].x += hb.w * w3.x; acc[j].y += hb.w * w3.y;
            acc[j].z += hb.w * w3.z; acc[j].w += hb.w * w3.w;
        }
    }

    // store k-slice partials: ps[ks][pos][j*4 .. j*4+4]
    float* pp = &ps[(ks * 32 + pos) * 20];
    *(float4*)&pp[0]  = acc[0];
    *(float4*)&pp[4]  = acc[1];
    *(float4*)&pp[8]  = acc[2];
    *(float4*)&pp[12] = acc[3];
    __syncthreads();

    // 128 cell owners: reduce 8 slices, pointwise, publish h
    if (tid < 128) {
        const int pos2 = tid >> 2;         // (u_l2, bq2)
        const int j    = tid & 3;
        const int u_l2 = pos2 >> 1;
        const int bq2  = pos2 & 1;
        const int b    = bq2 * 4 + j;
        const int ug   = (c0 >> 2) + u_l2; // global unit 0..511

        float4 g = make_float4(0.f, 0.f, 0.f, 0.f);
#pragma unroll
        for (int s = 0; s < 8; s++) {
            float4 p = *(const float4*)&ps[(s * 32 + pos2) * 20 + j * 4];
            g.x += p.x; g.y += p.y; g.z += p.z; g.w += p.w;
        }
        const size_t n = (size_t)((b0 + b) << 10) + t;
        float4 a = *(const float4*)&g_XW[n * 2048 + c0 + u_l2 * 4];
        float gi = g.x + a.x;              // bias already folded into XW
        float gf = g.y + a.y;
        float gg = g.z + a.z;
        float go = g.w + a.w;
        c = sigm_(gf) * c + sigm_(gi) * tanh_(gg);
        float h = sigm_(go) * tanh_(c);
        __stcg(&g_Hsave[n * NH + ug], h);  // L2-coherent publish
    }
    return c;
}

// ---------------- word LSTM, cooperative (1 launch, per-subgrid barriers) ----------
__global__ __launch_bounds__(WORD_THREADS, 1)
void word_coop_kernel(int /*dummy*/)
{
    extern __shared__ float sm[];
    float* ws = sm;
    float* hs = sm + WWS_FLOATS;
    float* ps = hs + WHS_FLOATS;

    const int tid = threadIdx.x;
    const int sub = blockIdx.x >> 5;               // subgrid 0..3
    const int cg_ = blockIdx.x & 31;               // CTA within subgrid
    const int c0  = cg_ * 64;
    const int b0  = sub * 8;

    word_fill_ws(ws, c0, tid);

    float c = 0.f;
    for (int t = 0; t < NS; t++) {
        c = word_step_body(ws, hs, ps, t, tid, c0, b0, c);

        // per-subgrid barrier: release (fence+add), acquire (spin+fence)
        __threadfence();
        __syncthreads();
        if (tid == 0) {
            atomicAdd(&g_bar4[sub], 1u);
            const unsigned target = (unsigned)(t + 1) * 32u;
            while (*(volatile unsigned int*)&g_bar4[sub] < target) __nanosleep(32);
            __threadfence();
        }
        __syncthreads();
    }
}

// ---------------- word LSTM fallback: one launch per step ----------------
__global__ __launch_bounds__(WORD_THREADS, 1)
void word_step_kernel(int t)
{
    extern __shared__ float sm[];
    float* ws = sm;
    float* hs = sm + WWS_FLOATS;
    float* ps = hs + WHS_FLOATS;

    const int tid = threadIdx.x;
    const int sub = blockIdx.x >> 5;
    const int cg_ = blockIdx.x & 31;
    const int c0  = cg_ * 64;
    const int b0  = sub * 8;

    word_fill_ws(ws, c0, tid);

    // cell-owner state indices (tid < 128)
    const int pos2 = tid >> 2;
    const int j    = tid & 3;
    const int u_l2 = pos2 >> 1;
    const int bq2  = pos2 & 1;
    const int b    = bq2 * 4 + j;
    const int ug   = (c0 >> 2) + u_l2;

    float c = 0.f;
    if (t > 0 && tid < 128) c = g_Cw[(b0 + b) * NH + ug];
    c = word_step_body(ws, hs, ps, t, tid, c0, b0, c);
    if (tid < 128) g_Cw[(b0 + b) * NH + ug] = c;
}

// ---------------- logits + log_softmax ----------------
__global__ __launch_bounds__(256, 1)
void logits_kernel(const float* __restrict__ Wt, const float* __restrict__ bt,
                   float* __restrict__ out)
{
    extern __shared__ float sm[];
    float* Wts = sm;               // [512][65]
    float* hs  = sm + 512 * 65;    // [4][512]
    __shared__ float sl[4][64];

    const int tid = threadIdx.x;
    for (int idx = tid; idx < 512 * 64; idx += 256) {
        int tg = idx >> 9, k = idx & 511;
        Wts[k * 65 + tg] = (tg < NT) ? Wt[tg * NH + k] : 0.f;
    }
    const int tokl = tid >> 6, tag = tid & 63;
    const int wid = tid >> 5, lane = tid & 31;
    float btv = (tag < NT) ? bt[tag] : 0.f;

    for (int tb = blockIdx.x; tb < NTOK / 4; tb += gridDim.x) {
        __syncthreads();
        for (int idx = tid; idx < 2048; idx += 256) {
            int tk = idx >> 9, k = idx & 511;
            hs[tk * 512 + k] = g_Hsave[(size_t)(tb * 4 + tk) * NH + k];
        }
        __syncthreads();
        float acc = 0.f;
#pragma unroll 8
        for (int k = 0; k < 512; k++)
            acc += hs[tokl * 512 + k] * Wts[k * 65 + tag];
        sl[tokl][tag] = (tag < NT) ? (acc + btv) : -1e30f;
        __syncthreads();
        if (wid < 4) {
            float l0 = sl[wid][lane], l1 = sl[wid][lane + 32];
            float m = fmaxf(l0, l1);
#pragma unroll
            for (int o = 16; o; o >>= 1) m = fmaxf(m, __shfl_xor_sync(0xffffffffu, m, o));
            float s = __expf(l0 - m) + __expf(l1 - m);
#pragma unroll
            for (int o = 16; o; o >>= 1) s += __shfl_xor_sync(0xffffffffu, s, o);
            float lse = m + __logf(s);
            int n = tb * 4 + wid;
            for (int j = lane; j < NT; j += 32)
                out[(size_t)n * NT + j] = sl[wid][j] - lse;
        }
    }
}

// ---------------- launch ----------------
extern "C" void kernel_launch(void* const* d_in, const int* in_sizes, int n_in,
                              void* d_out, int out_size)
{
    const int*   char_idx = (const int*)d_in[0];
    const int*   word_idx = (const int*)d_in[1];
    const float* char_emb = (const float*)d_in[2];
    const float* word_emb = (const float*)d_in[3];
    const float* Wc_ih    = (const float*)d_in[4];
    const float* Wc_hh    = (const float*)d_in[5];
    const float* bc       = (const float*)d_in[6];
    const float* Ww_ih    = (const float*)d_in[7];
    const float* Ww_hh    = (const float*)d_in[8];
    const float* bw       = (const float*)d_in[9];
    const float* Wt       = (const float*)d_in[10];
    const float* bt       = (const float*)d_in[11];
    float* out = (float*)d_out;

    const int word_smem   = WORD_SMEM_BYTES;             // 176256 B
    const int logits_smem = (512 * 65 + 4 * 512) * 4;    // 141312 B
    cudaFuncSetAttribute(word_coop_kernel,
                         cudaFuncAttributeMaxDynamicSharedMemorySize, word_smem);
    cudaFuncSetAttribute(word_step_kernel,
                         cudaFuncAttributeMaxDynamicSharedMemorySize, word_smem);
    cudaFuncSetAttribute(logits_kernel,
                         cudaFuncAttributeMaxDynamicSharedMemorySize, logits_smem);

    // Deterministic host-side decision: cooperative path only if the device
    // guarantees 128 co-resident CTAs (pure queries, capture-legal).
    int dev = 0;
    cudaGetDevice(&dev);
    int numSM = 0, coopAttr = 0, perSM = 0;
    cudaDeviceGetAttribute(&numSM, cudaDevAttrMultiProcessorCount, dev);
    cudaDeviceGetAttribute(&coopAttr, cudaDevAttrCooperativeLaunch, dev);
    cudaOccupancyMaxActiveBlocksPerMultiprocessor(&perSM, word_coop_kernel,
                                                  WORD_THREADS, word_smem);
    const bool coop_ok = (coopAttr != 0) && (perSM >= 1) && (numSM >= 128);

    prep_all_kernel<<<4096, 256>>>(Wc_ih, Wc_hh, bc, Ww_ih, Ww_hh, bw);

    for (int t = 0; t < NC; t++)
        char_step_kernel<<<dim3(NTOK / 64, 4), 256>>>(char_idx, char_emb, t);

    xw_kernel<<<dim3(NTOK / 64, 8), 256>>>(word_idx, word_emb);

    if (coop_ok) {
        int dummy = 0;
        void* kargs[] = { &dummy };
        cudaLaunchCooperativeKernel((void*)word_coop_kernel,
                                    dim3(128), dim3(WORD_THREADS),
                                    kargs, (size_t)word_smem, (cudaStream_t)0);
    } else {
        for (int t = 0; t < NS; t++)
            word_step_kernel<<<128, WORD_THREADS, word_smem>>>(t);
    }

    logits_kernel<<<148, 256, logits_smem>>>(Wt, bt, out);
}

// round 15
// speedup vs baseline: 2.2928x; 1.0396x over previous
#include <cuda_runtime.h>
#include <cuda_bf16.h>
#include <cooperative_groups.h>
#include <stdint.h>

namespace cg = cooperative_groups;

// Problem dims
#define NB 32
#define NS 1024
#define NC 12
#define NE 256
#define NH 512
#define NT 50
#define NTOK (NB*NS)          // 32768

// ---------------- device scratch (allocation-free) ----------------
__device__ float g_WcihT[NE * 4 * NE];            // [k=256][1024] col 4u+g <- row g*256+u
__device__ float g_WchhT[NE * 4 * NE];
__device__ float g_bcp[4 * NE];
__device__ float g_WwihT[2 * NE * 4 * NH];        // [k=512][2048]
__device__ float g_WwhhT[NH * 4 * NH];            // [k=512][2048]
__device__ float g_bwp[4 * NH];

__device__ float g_HcA[NTOK * NE];                // char h ping
__device__ float g_HcB[NTOK * NE];                // char h pong (holds final char_feat)
__device__ float g_Cc [NTOK * NE];                // char c state
__device__ float g_XW [(size_t)NTOK * 4 * NH];    // word-input preacts + bias, [n][2048]
__device__ float g_Hsave[(size_t)NTOK * NH];      // word hidden trace [n][512]
__device__ float g_Cw [NB * NH];                  // word c state (fallback path only)
__device__ unsigned int g_bar4[4];                // per-subgrid monotonic barrier counters

// ---------------- math helpers ----------------
__device__ __forceinline__ float sigm_(float x) {
    return __fdividef(1.f, 1.f + __expf(-x));
}
__device__ __forceinline__ float tanh_(float x) {
    return __fdividef(2.f, 1.f + __expf(-2.f * x)) - 1.f;
}

// ---------------- packed f32x2 helpers (sm_100+) ----------------
__device__ __forceinline__ unsigned long long splat2(float x) {
    unsigned long long r;
    asm("mov.b64 %0, {%1, %1};" : "=l"(r) : "f"(x));
    return r;
}
__device__ __forceinline__ void ffma2(unsigned long long& d,
                                      unsigned long long a, unsigned long long b) {
    asm("fma.rn.f32x2 %0, %1, %2, %0;" : "+l"(d) : "l"(a), "l"(b));
}
__device__ __forceinline__ float2 unpack2(unsigned long long v) {
    float2 f;
    asm("mov.b64 {%0, %1}, %2;" : "=f"(f.x), "=f"(f.y) : "l"(v));
    return f;
}

// ---------------- cp.async helpers ----------------
__device__ __forceinline__ void cpasync16(void* smem_dst, const void* gmem_src) {
    unsigned int d = (unsigned int)__cvta_generic_to_shared(smem_dst);
    asm volatile("cp.async.cg.shared.global [%0], [%1], 16;" :: "r"(d), "l"(gmem_src));
}
__device__ __forceinline__ void cpasync_commit() {
    asm volatile("cp.async.commit_group;" ::: "memory");
}
__device__ __forceinline__ void cpasync_wait0() {
    asm volatile("cp.async.wait_group 0;" ::: "memory");
}

// ---------------- prep: permute/transpose weights, zero barriers ----------------
__global__ void prep_all_kernel(const float* __restrict__ Wc_ih,
                                const float* __restrict__ Wc_hh,
                                const float* __restrict__ bc,
                                const float* __restrict__ Ww_ih,
                                const float* __restrict__ Ww_hh,
                                const float* __restrict__ bw)
{
    const int stride = gridDim.x * blockDim.x;
    for (int idx = blockIdx.x * blockDim.x + threadIdx.x; idx < 1048576; idx += stride) {
        // word weights: [k=512][c=2048], WT[k*2048 + (4u+g)] = W[(g*512+u)*Kdim + k]
        {
            int c = idx & 2047, k = idx >> 11;      // k in [0,512)
            int u = c >> 2, g = c & 3;
            g_WwihT[idx] = Ww_ih[(g * NH + u) * (2 * NE) + k];
            g_WwhhT[idx] = Ww_hh[(g * NH + u) * NH + k];
        }
        // char weights: [k=256][c=1024]
        if (idx < 262144) {
            int c = idx & 1023, k = idx >> 10;      // k in [0,256)
            int u = c >> 2, g = c & 3;
            g_WcihT[idx] = Wc_ih[(g * NE + u) * NE + k];
            g_WchhT[idx] = Wc_hh[(g * NE + u) * NE + k];
        }
        if (idx < 2048) {
            int u = idx >> 2, g = idx & 3;
            g_bwp[idx] = bw[g * NH + u];
        }
        if (idx < 1024) {
            int u = idx >> 2, g = idx & 3;
            g_bcp[idx] = bc[g * NE + u];
        }
        if (idx < 4) g_bar4[idx] = 0u;
    }
}

// ---------------- char LSTM step (FFMA2 + double-buffered cp.async pipeline) -------
// CTA: 64 tokens x 256 gate-cols. 2 chunk buffers; Ws via cp.async (no regs),
// Xs via 4-reg LDG prefetch. One __syncthreads per chunk.
__global__ __launch_bounds__(256, 2)
void char_step_kernel(const int* __restrict__ char_idx,
                      const float* __restrict__ char_emb, int t)
{
    __shared__ float Xs[2][16][68];     // [buf][k][token]
    __shared__ float Ws[2][16][260];    // [buf][k][col]
    __shared__ int   idxs[64];

    const int tid = threadIdx.x;
    const int tx = tid & 63;
    const int ty = tid >> 6;
    const int tok0 = blockIdx.x * 64;
    const int c0 = blockIdx.y * 256;
    const int xtok = tid >> 2, xkq = tid & 3;      // Xs load role

    float* hnew        = (t & 1) ? g_HcB : g_HcA;
    const float* hprev = (t & 1) ? g_HcA : g_HcB;

    unsigned long long acc2[8][4];   // [row-pair][col], packed f32x2
#pragma unroll
    for (int rp = 0; rp < 8; rp++) {
        acc2[rp][0] = 0ull; acc2[rp][1] = 0ull; acc2[rp][2] = 0ull; acc2[rp][3] = 0ull;
    }

    if (tid < 64) idxs[tid] = char_idx[(tok0 + tid) * NC + t];
    __syncthreads();

    const int nch = (t == 0) ? 16 : 32;            // chunks: pass*16 + kc

    // prologue: chunk 0
    float4 xv;
    {
        xv = *(const float4*)&char_emb[idxs[xtok] * NE + 0 + xkq * 4];
#pragma unroll
        for (int j = 0; j < 4; j++) {
            int f = tid + j * 256;
            int kk = f >> 6, cq = f & 63;
            cpasync16(&Ws[0][kk][cq * 4], &g_WcihT[kk * 1024 + c0 + cq * 4]);
        }
        cpasync_commit();
        Xs[0][xkq * 4 + 0][xtok] = xv.x;
        Xs[0][xkq * 4 + 1][xtok] = xv.y;
        Xs[0][xkq * 4 + 2][xtok] = xv.z;
        Xs[0][xkq * 4 + 3][xtok] = xv.w;
        cpasync_wait0();
        __syncthreads();
    }

    for (int cc = 0; cc < nch; cc++) {
        const int cur = cc & 1;
        const bool more = (cc + 1 < nch);
        if (more) {
            const int nc2 = cc + 1;
            const int k0n = (nc2 & 15) * 16;
            if (nc2 < 16)
                xv = *(const float4*)&char_emb[idxs[xtok] * NE + k0n + xkq * 4];
            else
                xv = *(const float4*)&hprev[(tok0 + xtok) * NE + k0n + xkq * 4];
            const float* W = (nc2 < 16) ? g_WcihT : g_WchhT;
#pragma unroll
            for (int j = 0; j < 4; j++) {
                int f = tid + j * 256;
                int kk = f >> 6, cq = f & 63;
                cpasync16(&Ws[cur ^ 1][kk][cq * 4], &W[(k0n + kk) * 1024 + c0 + cq * 4]);
            }
            cpasync_commit();
        }
#pragma unroll
        for (int k = 0; k < 16; k++) {
            float4 b = *(float4*)&Ws[cur][k][tx * 4];
            unsigned long long bs0 = splat2(b.x);
            unsigned long long bs1 = splat2(b.y);
            unsigned long long bs2 = splat2(b.z);
            unsigned long long bs3 = splat2(b.w);
            ulonglong2 A0 = *(const ulonglong2*)&Xs[cur][k][ty * 16 + 0];
            ulonglong2 A1 = *(const ulonglong2*)&Xs[cur][k][ty * 16 + 4];
            ulonglong2 A2 = *(const ulonglong2*)&Xs[cur][k][ty * 16 + 8];
            ulonglong2 A3 = *(const ulonglong2*)&Xs[cur][k][ty * 16 + 12];
            unsigned long long ap[8] = {A0.x, A0.y, A1.x, A1.y, A2.x, A2.y, A3.x, A3.y};
#pragma unroll
            for (int rp = 0; rp < 8; rp++) {
                ffma2(acc2[rp][0], ap[rp], bs0);
                ffma2(acc2[rp][1], ap[rp], bs1);
                ffma2(acc2[rp][2], ap[rp], bs2);
                ffma2(acc2[rp][3], ap[rp], bs3);
            }
        }
        if (more) {
            Xs[cur ^ 1][xkq * 4 + 0][xtok] = xv.x;
            Xs[cur ^ 1][xkq * 4 + 1][xtok] = xv.y;
            Xs[cur ^ 1][xkq * 4 + 2][xtok] = xv.z;
            Xs[cur ^ 1][xkq * 4 + 3][xtok] = xv.w;
            cpasync_wait0();
            __syncthreads();
        }
    }

    const int u = (c0 >> 2) + tx;                  // global unit 0..255
    float4 bias = *(const float4*)&g_bcp[c0 + tx * 4];
#pragma unroll
    for (int rp = 0; rp < 8; rp++) {
        float2 gi2 = unpack2(acc2[rp][0]);
        float2 gf2 = unpack2(acc2[rp][1]);
        float2 gg2 = unpack2(acc2[rp][2]);
        float2 go2 = unpack2(acc2[rp][3]);
#pragma unroll
        for (int hh = 0; hh < 2; hh++) {
            int tok = tok0 + ty * 16 + rp * 2 + hh;
            float gi = (hh ? gi2.y : gi2.x) + bias.x;
            float gf = (hh ? gf2.y : gf2.x) + bias.y;
            float gg = (hh ? gg2.y : gg2.x) + bias.z;
            float go = (hh ? go2.y : go2.x) + bias.w;
            float cp = (t == 0) ? 0.f : g_Cc[tok * NE + u];
            float cn = sigm_(gf) * cp + sigm_(gi) * tanh_(gg);
            float h  = sigm_(go) * tanh_(cn);
            g_Cc[tok * NE + u] = cn;
            hnew[tok * NE + u] = h;
        }
    }
}

// ---------------- word-input GEMM: XW (FFMA2 + double-buffered pipeline) -----------
__global__ __launch_bounds__(256, 2)
void xw_kernel(const int* __restrict__ word_idx, const float* __restrict__ word_emb)
{
    __shared__ float Xs[2][16][68];
    __shared__ float Ws[2][16][260];
    __shared__ int   idxs[64];

    const int tid = threadIdx.x;
    const int tx = tid & 63;
    const int ty = tid >> 6;
    const int tok0 = blockIdx.x * 64;
    const int c0 = blockIdx.y * 256;
    const int xtok = tid >> 2, xkq = tid & 3;

    unsigned long long acc2[8][4];
#pragma unroll
    for (int rp = 0; rp < 8; rp++) {
        acc2[rp][0] = 0ull; acc2[rp][1] = 0ull; acc2[rp][2] = 0ull; acc2[rp][3] = 0ull;
    }

    if (tid < 64) idxs[tid] = word_idx[tok0 + tid];
    __syncthreads();

    const int nch = 32;

    float4 xv;
    {
        xv = *(const float4*)&word_emb[(size_t)idxs[xtok] * NE + xkq * 4];
#pragma unroll
        for (int j = 0; j < 4; j++) {
            int f = tid + j * 256;
            int kk = f >> 6, cq = f & 63;
            cpasync16(&Ws[0][kk][cq * 4], &g_WwihT[kk * 2048 + c0 + cq * 4]);
        }
        cpasync_commit();
        Xs[0][xkq * 4 + 0][xtok] = xv.x;
        Xs[0][xkq * 4 + 1][xtok] = xv.y;
        Xs[0][xkq * 4 + 2][xtok] = xv.z;
        Xs[0][xkq * 4 + 3][xtok] = xv.w;
        cpasync_wait0();
        __syncthreads();
    }

    for (int cc = 0; cc < nch; cc++) {
        const int cur = cc & 1;
        const bool more = (cc + 1 < nch);
        if (more) {
            const int nc2 = cc + 1;
            const int k0n = nc2 * 16;
            if (nc2 < 16)
                xv = *(const float4*)&word_emb[(size_t)idxs[xtok] * NE + k0n + xkq * 4];
            else
                xv = *(const float4*)&g_HcB[(tok0 + xtok) * NE + (k0n - NE) + xkq * 4];
#pragma unroll
            for (int j = 0; j < 4; j++) {
                int f = tid + j * 256;
                int kk = f >> 6, cq = f & 63;
                cpasync16(&Ws[cur ^ 1][kk][cq * 4],
                          &g_WwihT[(k0n + kk) * 2048 + c0 + cq * 4]);
            }
            cpasync_commit();
        }
#pragma unroll
        for (int k = 0; k < 16; k++) {
            float4 b = *(float4*)&Ws[cur][k][tx * 4];
            unsigned long long bs0 = splat2(b.x);
            unsigned long long bs1 = splat2(b.y);
            unsigned long long bs2 = splat2(b.z);
            unsigned long long bs3 = splat2(b.w);
            ulonglong2 A0 = *(const ulonglong2*)&Xs[cur][k][ty * 16 + 0];
            ulonglong2 A1 = *(const ulonglong2*)&Xs[cur][k][ty * 16 + 4];
            ulonglong2 A2 = *(const ulonglong2*)&Xs[cur][k][ty * 16 + 8];
            ulonglong2 A3 = *(const ulonglong2*)&Xs[cur][k][ty * 16 + 12];
            unsigned long long ap[8] = {A0.x, A0.y, A1.x, A1.y, A2.x, A2.y, A3.x, A3.y};
#pragma unroll
            for (int rp = 0; rp < 8; rp++) {
                ffma2(acc2[rp][0], ap[rp], bs0);
                ffma2(acc2[rp][1], ap[rp], bs1);
                ffma2(acc2[rp][2], ap[rp], bs2);
                ffma2(acc2[rp][3], ap[rp], bs3);
            }
        }
        if (more) {
            Xs[cur ^ 1][xkq * 4 + 0][xtok] = xv.x;
            Xs[cur ^ 1][xkq * 4 + 1][xtok] = xv.y;
            Xs[cur ^ 1][xkq * 4 + 2][xtok] = xv.z;
            Xs[cur ^ 1][xkq * 4 + 3][xtok] = xv.w;
            cpasync_wait0();
            __syncthreads();
        }
    }

    float4 bias = *(const float4*)&g_bwp[c0 + tx * 4];
#pragma unroll
    for (int rp = 0; rp < 8; rp++) {
        float2 o0 = unpack2(acc2[rp][0]);
        float2 o1 = unpack2(acc2[rp][1]);
        float2 o2 = unpack2(acc2[rp][2]);
        float2 o3 = unpack2(acc2[rp][3]);
#pragma unroll
        for (int hh = 0; hh < 2; hh++) {
            int tok = tok0 + ty * 16 + rp * 2 + hh;
            float4 o;
            o.x = (hh ? o0.y : o0.x) + bias.x;
            o.y = (hh ? o1.y : o1.x) + bias.y;
            o.z = (hh ? o2.y : o2.x) + bias.z;
            o.w = (hh ? o3.y : o3.x) + bias.w;
            *(float4*)&g_XW[(size_t)tok * 2048 + c0 + tx * 4] = o;
        }
    }
}

// ---------------- word LSTM: subgrid decomposition + high-reuse dot (R12) ----------
#define WWS_STRIDE 68
#define WWS_FLOATS (512 * WWS_STRIDE)
#define WHS_STRIDE 516
#define WHS_FLOATS (8 * WHS_STRIDE)
#define WPS_FLOATS (8 * 32 * 20)
#define WORD_SMEM_BYTES ((WWS_FLOATS + WHS_FLOATS + WPS_FLOATS) * 4)
#define WORD_THREADS 256

__device__ __forceinline__ void word_fill_ws(float* ws, int c0, int tid)
{
    for (int idx = tid; idx < 512 * 64; idx += WORD_THREADS) {
        int k = idx >> 6, j = idx & 63;
        ws[k * WWS_STRIDE + j] = g_WwhhT[k * 2048 + c0 + j];
    }
}

__device__ __forceinline__ void word_fill_hs(float* hs, int t, int b0, int tid)
{
    if (t == 0) {
        for (int i = tid; i < WHS_FLOATS; i += WORD_THREADS) hs[i] = 0.f;
    } else {
#pragma unroll 4
        for (int i = tid; i < 1024; i += WORD_THREADS) {
            int bb = i >> 7, k4 = i & 127;
            float4 v = __ldcg((const float4*)&g_Hsave[
                (size_t)(((b0 + bb) << 10) + (t - 1)) * NH + k4 * 4]);
            *(float4*)&hs[bb * WHS_STRIDE + k4 * 4] = v;
        }
    }
}

__device__ __forceinline__ float word_step_body(float* ws, float* hs, float* ps,
                                                int t, int tid, int c0, int b0, float c)
{
    const int ks  = tid >> 5;
    const int pos = tid & 31;
    const int u_l = pos >> 1;
    const int bq  = pos & 1;
    const int k0  = ks * 64;

    word_fill_hs(hs, t, b0, tid);
    __syncthreads();

    float4 acc[4];
    acc[0] = make_float4(0.f, 0.f, 0.f, 0.f);
    acc[1] = make_float4(0.f, 0.f, 0.f, 0.f);
    acc[2] = make_float4(0.f, 0.f, 0.f, 0.f);
    acc[3] = make_float4(0.f, 0.f, 0.f, 0.f);

    const float* hbase = &hs[(bq * 4) * WHS_STRIDE];
#pragma unroll 4
    for (int k = k0; k < k0 + 64; k += 4) {
        float4 w0 = *(const float4*)&ws[(k + 0) * WWS_STRIDE + u_l * 4];
        float4 w1 = *(const float4*)&ws[(k + 1) * WWS_STRIDE + u_l * 4];
        float4 w2 = *(const float4*)&ws[(k + 2) * WWS_STRIDE + u_l * 4];
        float4 w3 = *(const float4*)&ws[(k + 3) * WWS_STRIDE + u_l * 4];
#pragma unroll
        for (int j = 0; j < 4; j++) {
            float4 hb = *(const float4*)&hbase[j * WHS_STRIDE + k];
            acc[j].x += hb.x * w0.x; acc[j].y += hb.x * w0.y;
            acc[j].z += hb.x * w0.z; acc[j].w += hb.x * w0.w;
            acc[j].x += hb.y * w1.x; acc[j].y += hb.y * w1.y;
            acc[j].z += hb.y * w1.z; acc[j].w += hb.y * w1.w;
            acc[j].x += hb.z * w2.x; acc[j].y += hb.z * w2.y;
            acc[j].z += hb.z * w2.z; acc[j].w += hb.z * w2.w;
            acc[j].x += hb.w * w3.x; acc[j].y += hb.w * w3.y;
            acc[j].z += hb.w * w3.z; acc[j].w += hb.w * w3.w;
        }
    }

    float* pp = &ps[(ks * 32 + pos) * 20];
    *(float4*)&pp[0]  = acc[0];
    *(float4*)&pp[4]  = acc[1];
    *(float4*)&pp[8]  = acc[2];
    *(float4*)&pp[12] = acc[3];
    __syncthreads();

    if (tid < 128) {
        const int pos2 = tid >> 2;
        const int j    = tid & 3;
        const int u_l2 = pos2 >> 1;
        const int bq2  = pos2 & 1;
        const int b    = bq2 * 4 + j;
        const int ug   = (c0 >> 2) + u_l2;

        float4 g = make_float4(0.f, 0.f, 0.f, 0.f);
#pragma unroll
        for (int s = 0; s < 8; s++) {
            float4 p = *(const float4*)&ps[(s * 32 + pos2) * 20 + j * 4];
            g.x += p.x; g.y += p.y; g.z += p.z; g.w += p.w;
        }
        const size_t n = (size_t)((b0 + b) << 10) + t;
        float4 a = *(const float4*)&g_XW[n * 2048 + c0 + u_l2 * 4];
        float gi = g.x + a.x;
        float gf = g.y + a.y;
        float gg = g.z + a.z;
        float go = g.w + a.w;
        c = sigm_(gf) * c + sigm_(gi) * tanh_(gg);
        float h = sigm_(go) * tanh_(c);
        __stcg(&g_Hsave[n * NH + ug], h);
    }
    return c;
}

__global__ __launch_bounds__(WORD_THREADS, 1)
void word_coop_kernel(int /*dummy*/)
{
    extern __shared__ float sm[];
    float* ws = sm;
    float* hs = sm + WWS_FLOATS;
    float* ps = hs + WHS_FLOATS;

    const int tid = threadIdx.x;
    const int sub = blockIdx.x >> 5;
    const int cg_ = blockIdx.x & 31;
    const int c0  = cg_ * 64;
    const int b0  = sub * 8;

    word_fill_ws(ws, c0, tid);

    float c = 0.f;
    for (int t = 0; t < NS; t++) {
        c = word_step_body(ws, hs, ps, t, tid, c0, b0, c);

        __threadfence();
        __syncthreads();
        if (tid == 0) {
            atomicAdd(&g_bar4[sub], 1u);
            const unsigned target = (unsigned)(t + 1) * 32u;
            while (*(volatile unsigned int*)&g_bar4[sub] < target) __nanosleep(32);
            __threadfence();
        }
        __syncthreads();
    }
}

__global__ __launch_bounds__(WORD_THREADS, 1)
void word_step_kernel(int t)
{
    extern __shared__ float sm[];
    float* ws = sm;
    float* hs = sm + WWS_FLOATS;
    float* ps = hs + WHS_FLOATS;

    const int tid = threadIdx.x;
    const int sub = blockIdx.x >> 5;
    const int cg_ = blockIdx.x & 31;
    const int c0  = cg_ * 64;
    const int b0  = sub * 8;

    word_fill_ws(ws, c0, tid);

    const int pos2 = tid >> 2;
    const int j    = tid & 3;
    const int u_l2 = pos2 >> 1;
    const int bq2  = pos2 & 1;
    const int b    = bq2 * 4 + j;
    const int ug   = (c0 >> 2) + u_l2;

    float c = 0.f;
    if (t > 0 && tid < 128) c = g_Cw[(b0 + b) * NH + ug];
    c = word_step_body(ws, hs, ps, t, tid, c0, b0, c);
    if (tid < 128) g_Cw[(b0 + b) * NH + ug] = c;
}

// ---------------- logits + log_softmax ----------------
__global__ __launch_bounds__(256, 1)
void logits_kernel(const float* __restrict__ Wt, const float* __restrict__ bt,
                   float* __restrict__ out)
{
    extern __shared__ float sm[];
    float* Wts = sm;               // [512][65]
    float* hs  = sm + 512 * 65;    // [4][512]
    __shared__ float sl[4][64];

    const int tid = threadIdx.x;
    for (int idx = tid; idx < 512 * 64; idx += 256) {
        int tg = idx >> 9, k = idx & 511;
        Wts[k * 65 + tg] = (tg < NT) ? Wt[tg * NH + k] : 0.f;
    }
    const int tokl = tid >> 6, tag = tid & 63;
    const int wid = tid >> 5, lane = tid & 31;
    float btv = (tag < NT) ? bt[tag] : 0.f;

    for (int tb = blockIdx.x; tb < NTOK / 4; tb += gridDim.x) {
        __syncthreads();
        for (int idx = tid; idx < 2048; idx += 256) {
            int tk = idx >> 9, k = idx & 511;
            hs[tk * 512 + k] = g_Hsave[(size_t)(tb * 4 + tk) * NH + k];
        }
        __syncthreads();
        float acc = 0.f;
#pragma unroll 8
        for (int k = 0; k < 512; k++)
            acc += hs[tokl * 512 + k] * Wts[k * 65 + tag];
        sl[tokl][tag] = (tag < NT) ? (acc + btv) : -1e30f;
        __syncthreads();
        if (wid < 4) {
            float l0 = sl[wid][lane], l1 = sl[wid][lane + 32];
            float m = fmaxf(l0, l1);
#pragma unroll
            for (int o = 16; o; o >>= 1) m = fmaxf(m, __shfl_xor_sync(0xffffffffu, m, o));
            float s = __expf(l0 - m) + __expf(l1 - m);
#pragma unroll
            for (int o = 16; o; o >>= 1) s += __shfl_xor_sync(0xffffffffu, s, o);
            float lse = m + __logf(s);
            int n = tb * 4 + wid;
            for (int j = lane; j < NT; j += 32)
                out[(size_t)n * NT + j] = sl[wid][j] - lse;
        }
    }
}

// ---------------- launch ----------------
extern "C" void kernel_launch(void* const* d_in, const int* in_sizes, int n_in,
                              void* d_out, int out_size)
{
    const int*   char_idx = (const int*)d_in[0];
    const int*   word_idx = (const int*)d_in[1];
    const float* char_emb = (const float*)d_in[2];
    const float* word_emb = (const float*)d_in[3];
    const float* Wc_ih    = (const float*)d_in[4];
    const float* Wc_hh    = (const float*)d_in[5];
    const float* bc       = (const float*)d_in[6];
    const float* Ww_ih    = (const float*)d_in[7];
    const float* Ww_hh    = (const float*)d_in[8];
    const float* bw       = (const float*)d_in[9];
    const float* Wt       = (const float*)d_in[10];
    const float* bt       = (const float*)d_in[11];
    float* out = (float*)d_out;

    const int word_smem   = WORD_SMEM_BYTES;             // 176256 B
    const int logits_smem = (512 * 65 + 4 * 512) * 4;    // 141312 B
    cudaFuncSetAttribute(word_coop_kernel,
                         cudaFuncAttributeMaxDynamicSharedMemorySize, word_smem);
    cudaFuncSetAttribute(word_step_kernel,
                         cudaFuncAttributeMaxDynamicSharedMemorySize, word_smem);
    cudaFuncSetAttribute(logits_kernel,
                         cudaFuncAttributeMaxDynamicSharedMemorySize, logits_smem);

    // Deterministic host-side decision: cooperative path only if the device
    // guarantees 128 co-resident CTAs (pure queries, capture-legal).
    int dev = 0;
    cudaGetDevice(&dev);
    int numSM = 0, coopAttr = 0, perSM = 0;
    cudaDeviceGetAttribute(&numSM, cudaDevAttrMultiProcessorCount, dev);
    cudaDeviceGetAttribute(&coopAttr, cudaDevAttrCooperativeLaunch, dev);
    cudaOccupancyMaxActiveBlocksPerMultiprocessor(&perSM, word_coop_kernel,
                                                  WORD_THREADS, word_smem);
    const bool coop_ok = (coopAttr != 0) && (perSM >= 1) && (numSM >= 128);

    prep_all_kernel<<<4096, 256>>>(Wc_ih, Wc_hh, bc, Ww_ih, Ww_hh, bw);

    for (int t = 0; t < NC; t++)
        char_step_kernel<<<dim3(NTOK / 64, 4), 256>>>(char_idx, char_emb, t);

    xw_kernel<<<dim3(NTOK / 64, 8), 256>>>(word_idx, word_emb);

    if (coop_ok) {
        int dummy = 0;
        void* kargs[] = { &dummy };
        cudaLaunchCooperativeKernel((void*)word_coop_kernel,
                                    dim3(128), dim3(WORD_THREADS),
                                    kargs, (size_t)word_smem, (cudaStream_t)0);
    } else {
        for (int t = 0; t < NS; t++)
            word_step_kernel<<<128, WORD_THREADS, word_smem>>>(t);
    }

    logits_kernel<<<148, 256, logits_smem>>>(Wt, bt, out);
}

// round 17
// speedup vs baseline: 3.1214x; 1.3614x over previous
#include <cuda_runtime.h>
#include <cuda_bf16.h>
#include <cooperative_groups.h>
#include <stdint.h>

namespace cg = cooperative_groups;

// Problem dims
#define NB 32
#define NS 1024
#define NC 12
#define NE 256
#define NH 512
#define NT 50
#define NCS 128
#define NTOK (NB*NS)          // 32768

// ---------------- device scratch (allocation-free) ----------------
__device__ float g_WcihT[NE * 4 * NE];            // [k=256][1024] col 4u+g <- row g*256+u
__device__ float g_WchhT[NE * 4 * NE];
__device__ float g_bcp[4 * NE];
__device__ float g_Eih[NCS * 4 * NE];             // [cs][1024]: bc + emb(cs) @ WcihT
__device__ float g_WwihT[2 * NE * 4 * NH];        // [k=512][2048]
__device__ float g_WwhhT[NH * 4 * NH];            // [k=512][2048]
__device__ float g_bwp[4 * NH];

__device__ float g_HcA[NTOK * NE];                // char h ping
__device__ float g_HcB[NTOK * NE];                // char h pong (holds final char_feat)
__device__ float g_Cc [NTOK * NE];                // char c state
__device__ float g_XW [(size_t)NTOK * 4 * NH];    // word-input preacts + bias, [n][2048]
__device__ float g_Hsave[(size_t)NTOK * NH];      // word hidden trace [n][512]
__device__ float g_Cw [NB * NH];                  // word c state (fallback path only)
__device__ unsigned int g_bar4[4];                // per-subgrid monotonic barrier counters

// ---------------- math helpers ----------------
__device__ __forceinline__ float sigm_(float x) {
    return __fdividef(1.f, 1.f + __expf(-x));
}
__device__ __forceinline__ float tanh_(float x) {
    return __fdividef(2.f, 1.f + __expf(-2.f * x)) - 1.f;
}

// ---------------- packed f32x2 helpers (sm_100+) ----------------
__device__ __forceinline__ unsigned long long splat2(float x) {
    unsigned long long r;
    asm("mov.b64 %0, {%1, %1};" : "=l"(r) : "f"(x));
    return r;
}
__device__ __forceinline__ unsigned long long pack2(float lo, float hi) {
    unsigned long long r;
    asm("mov.b64 %0, {%1, %2};" : "=l"(r) : "f"(lo), "f"(hi));
    return r;
}
__device__ __forceinline__ void ffma2(unsigned long long& d,
                                      unsigned long long a, unsigned long long b) {
    asm("fma.rn.f32x2 %0, %1, %2, %0;" : "+l"(d) : "l"(a), "l"(b));
}
__device__ __forceinline__ float2 unpack2(unsigned long long v) {
    float2 f;
    asm("mov.b64 {%0, %1}, %2;" : "=f"(f.x), "=f"(f.y) : "l"(v));
    return f;
}

// ---------------- cp.async helpers ----------------
__device__ __forceinline__ void cpasync16(void* smem_dst, const void* gmem_src) {
    unsigned int d = (unsigned int)__cvta_generic_to_shared(smem_dst);
    asm volatile("cp.async.cg.shared.global [%0], [%1], 16;" :: "r"(d), "l"(gmem_src));
}
__device__ __forceinline__ void cpasync_commit() {
    asm volatile("cp.async.commit_group;" ::: "memory");
}
__device__ __forceinline__ void cpasync_wait0() {
    asm volatile("cp.async.wait_group 0;" ::: "memory");
}

// ---------------- prep: permute/transpose weights, zero barriers ----------------
__global__ void prep_all_kernel(const float* __restrict__ Wc_ih,
                                const float* __restrict__ Wc_hh,
                                const float* __restrict__ bc,
                                const float* __restrict__ Ww_ih,
                                const float* __restrict__ Ww_hh,
                                const float* __restrict__ bw)
{
    const int stride = gridDim.x * blockDim.x;
    for (int idx = blockIdx.x * blockDim.x + threadIdx.x; idx < 1048576; idx += stride) {
        // word weights: [k=512][c=2048], WT[k*2048 + (4u+g)] = W[(g*512+u)*Kdim + k]
        {
            int c = idx & 2047, k = idx >> 11;      // k in [0,512)
            int u = c >> 2, g = c & 3;
            g_WwihT[idx] = Ww_ih[(g * NH + u) * (2 * NE) + k];
            g_WwhhT[idx] = Ww_hh[(g * NH + u) * NH + k];
        }
        // char weights: [k=256][c=1024]
        if (idx < 262144) {
            int c = idx & 1023, k = idx >> 10;      // k in [0,256)
            int u = c >> 2, g = c & 3;
            g_WcihT[idx] = Wc_ih[(g * NE + u) * NE + k];
            g_WchhT[idx] = Wc_hh[(g * NE + u) * NE + k];
        }
        if (idx < 2048) {
            int u = idx >> 2, g = idx & 3;
            g_bwp[idx] = bw[g * NH + u];
        }
        if (idx < 1024) {
            int u = idx >> 2, g = idx & 3;
            g_bcp[idx] = bc[g * NE + u];
        }
        if (idx < 4) g_bar4[idx] = 0u;
    }
}

// ---------------- E table: Eih[cs][c] = bcp[c] + emb[cs] @ WcihT ----------------
// One CTA per charset entry; 256 threads x 4 cols each.
__global__ __launch_bounds__(256, 4)
void eih_kernel(const float* __restrict__ char_emb)
{
    __shared__ float emb[NE];
    const int cs = blockIdx.x;
    const int tid = threadIdx.x;
    if (tid < NE) emb[tid] = char_emb[cs * NE + tid];
    __syncthreads();

    const int c = tid * 4;
    float4 acc = *(const float4*)&g_bcp[c];
#pragma unroll 8
    for (int k = 0; k < NE; k++) {
        float e = emb[k];
        float4 w = *(const float4*)&g_WcihT[k * 1024 + c];
        acc.x += e * w.x; acc.y += e * w.y; acc.z += e * w.z; acc.w += e * w.w;
    }
    *(float4*)&g_Eih[cs * 1024 + c] = acc;
}

// ---------------- char t=0: pointwise only (h = f(E[char0]), c0 = 0) ----------------
// One thread per (token, unit-quad is split: thread handles 1 unit via float4 read).
__global__ __launch_bounds__(256, 8)
void char_init_kernel(const int* __restrict__ char_idx)
{
    const int gid = blockIdx.x * 256 + threadIdx.x;   // 0 .. NTOK*NE-1
    const int tok = gid >> 8;
    const int u   = gid & 255;
    const int cs  = __ldg(&char_idx[tok * NC]);
    float4 e = *(const float4*)&g_Eih[cs * 1024 + u * 4];
    float c = sigm_(e.x) * tanh_(e.z);                // f-gate * c0(=0) dropped
    float h = sigm_(e.w) * tanh_(c);
    g_Cc [tok * NE + u] = c;
    g_HcA[tok * NE + u] = h;
}

// ---------------- char LSTM step t>=1 (hh GEMM only; acc seeded from E gather) -----
// CTA: 64 tokens x 256 gate-cols. Double-buffered cp.async pipeline over 16 chunks.
__global__ __launch_bounds__(256, 2)
void char_step_kernel(const int* __restrict__ char_idx, int t)
{
    __shared__ float Xs[2][16][68];     // [buf][k][token]  (hprev, transposed)
    __shared__ float Ws[2][16][260];    // [buf][k][col]    (Whh)
    __shared__ int   idxs[64];

    const int tid = threadIdx.x;
    const int tx = tid & 63;
    const int ty = tid >> 6;
    const int tok0 = blockIdx.x * 64;
    const int c0 = blockIdx.y * 256;
    const int xtok = tid >> 2, xkq = tid & 3;      // Xs load role

    float* hnew        = (t & 1) ? g_HcB : g_HcA;
    const float* hprev = (t & 1) ? g_HcA : g_HcB;

    if (tid < 64) idxs[tid] = char_idx[(tok0 + tid) * NC + t];
    __syncthreads();

    // prologue: chunk 0 (Ws via cp.async, Xs via registers)
    float4 xv;
    {
        xv = *(const float4*)&hprev[(tok0 + xtok) * NE + xkq * 4];
#pragma unroll
        for (int j = 0; j < 4; j++) {
            int f = tid + j * 256;
            int kk = f >> 6, cq = f & 63;
            cpasync16(&Ws[0][kk][cq * 4], &g_WchhT[kk * 1024 + c0 + cq * 4]);
        }
        cpasync_commit();
    }

    // acc seeded from E gather (ih preacts + bias), overlapping the prologue loads
    unsigned long long acc2[8][4];
#pragma unroll
    for (int rp = 0; rp < 8; rp++) {
        const int tA = ty * 16 + rp * 2;
        float4 eA = *(const float4*)&g_Eih[idxs[tA] * 1024 + c0 + tx * 4];
        float4 eB = *(const float4*)&g_Eih[idxs[tA + 1] * 1024 + c0 + tx * 4];
        acc2[rp][0] = pack2(eA.x, eB.x);
        acc2[rp][1] = pack2(eA.y, eB.y);
        acc2[rp][2] = pack2(eA.z, eB.z);
        acc2[rp][3] = pack2(eA.w, eB.w);
    }

    {
        Xs[0][xkq * 4 + 0][xtok] = xv.x;
        Xs[0][xkq * 4 + 1][xtok] = xv.y;
        Xs[0][xkq * 4 + 2][xtok] = xv.z;
        Xs[0][xkq * 4 + 3][xtok] = xv.w;
        cpasync_wait0();
        __syncthreads();
    }

    const int nch = 16;
    for (int cc = 0; cc < nch; cc++) {
        const int cur = cc & 1;
        const bool more = (cc + 1 < nch);
        if (more) {
            const int k0n = (cc + 1) * 16;
            xv = *(const float4*)&hprev[(tok0 + xtok) * NE + k0n + xkq * 4];
#pragma unroll
            for (int j = 0; j < 4; j++) {
                int f = tid + j * 256;
                int kk = f >> 6, cq = f & 63;
                cpasync16(&Ws[cur ^ 1][kk][cq * 4],
                          &g_WchhT[(k0n + kk) * 1024 + c0 + cq * 4]);
            }
            cpasync_commit();
        }
#pragma unroll
        for (int k = 0; k < 16; k++) {
            float4 b = *(float4*)&Ws[cur][k][tx * 4];
            unsigned long long bs0 = splat2(b.x);
            unsigned long long bs1 = splat2(b.y);
            unsigned long long bs2 = splat2(b.z);
            unsigned long long bs3 = splat2(b.w);
            ulonglong2 A0 = *(const ulonglong2*)&Xs[cur][k][ty * 16 + 0];
            ulonglong2 A1 = *(const ulonglong2*)&Xs[cur][k][ty * 16 + 4];
            ulonglong2 A2 = *(const ulonglong2*)&Xs[cur][k][ty * 16 + 8];
            ulonglong2 A3 = *(const ulonglong2*)&Xs[cur][k][ty * 16 + 12];
            unsigned long long ap[8] = {A0.x, A0.y, A1.x, A1.y, A2.x, A2.y, A3.x, A3.y};
#pragma unroll
            for (int rp = 0; rp < 8; rp++) {
                ffma2(acc2[rp][0], ap[rp], bs0);
                ffma2(acc2[rp][1], ap[rp], bs1);
                ffma2(acc2[rp][2], ap[rp], bs2);
                ffma2(acc2[rp][3], ap[rp], bs3);
            }
        }
        if (more) {
            Xs[cur ^ 1][xkq * 4 + 0][xtok] = xv.x;
            Xs[cur ^ 1][xkq * 4 + 1][xtok] = xv.y;
            Xs[cur ^ 1][xkq * 4 + 2][xtok] = xv.z;
            Xs[cur ^ 1][xkq * 4 + 3][xtok] = xv.w;
            cpasync_wait0();
            __syncthreads();
        }
    }

    // fused LSTM pointwise epilogue (bias already inside E)
    const int u = (c0 >> 2) + tx;                  // global unit 0..255
#pragma unroll
    for (int rp = 0; rp < 8; rp++) {
        float2 gi2 = unpack2(acc2[rp][0]);
        float2 gf2 = unpack2(acc2[rp][1]);
        float2 gg2 = unpack2(acc2[rp][2]);
        float2 go2 = unpack2(acc2[rp][3]);
#pragma unroll
        for (int hh = 0; hh < 2; hh++) {
            int tok = tok0 + ty * 16 + rp * 2 + hh;
            float gi = (hh ? gi2.y : gi2.x);
            float gf = (hh ? gf2.y : gf2.x);
            float gg = (hh ? gg2.y : gg2.x);
            float go = (hh ? go2.y : go2.x);
            float cp = g_Cc[tok * NE + u];
            float cn = sigm_(gf) * cp + sigm_(gi) * tanh_(gg);
            float h  = sigm_(go) * tanh_(cn);
            g_Cc[tok * NE + u] = cn;
            hnew[tok * NE + u] = h;
        }
    }
}

// ---------------- word-input GEMM: XW (FFMA2 + double-buffered pipeline) -----------
__global__ __launch_bounds__(256, 2)
void xw_kernel(const int* __restrict__ word_idx, const float* __restrict__ word_emb)
{
    __shared__ float Xs[2][16][68];
    __shared__ float Ws[2][16][260];
    __shared__ int   idxs[64];

    const int tid = threadIdx.x;
    const int tx = tid & 63;
    const int ty = tid >> 6;
    const int tok0 = blockIdx.x * 64;
    const int c0 = blockIdx.y * 256;
    const int xtok = tid >> 2, xkq = tid & 3;

    unsigned long long acc2[8][4];
#pragma unroll
    for (int rp = 0; rp < 8; rp++) {
        acc2[rp][0] = 0ull; acc2[rp][1] = 0ull; acc2[rp][2] = 0ull; acc2[rp][3] = 0ull;
    }

    if (tid < 64) idxs[tid] = word_idx[tok0 + tid];
    __syncthreads();

    const int nch = 32;

    float4 xv;
    {
        xv = *(const float4*)&word_emb[(size_t)idxs[xtok] * NE + xkq * 4];
#pragma unroll
        for (int j = 0; j < 4; j++) {
            int f = tid + j * 256;
            int kk = f >> 6, cq = f & 63;
            cpasync16(&Ws[0][kk][cq * 4], &g_WwihT[kk * 2048 + c0 + cq * 4]);
        }
        cpasync_commit();
        Xs[0][xkq * 4 + 0][xtok] = xv.x;
        Xs[0][xkq * 4 + 1][xtok] = xv.y;
        Xs[0][xkq * 4 + 2][xtok] = xv.z;
        Xs[0][xkq * 4 + 3][xtok] = xv.w;
        cpasync_wait0();
        __syncthreads();
    }

    for (int cc = 0; cc < nch; cc++) {
        const int cur = cc & 1;
        const bool more = (cc + 1 < nch);
        if (more) {
            const int nc2 = cc + 1;
            const int k0n = nc2 * 16;
            if (nc2 < 16)
                xv = *(const float4*)&word_emb[(size_t)idxs[xtok] * NE + k0n + xkq * 4];
            else
                xv = *(const float4*)&g_HcB[(tok0 + xtok) * NE + (k0n - NE) + xkq * 4];
#pragma unroll
            for (int j = 0; j < 4; j++) {
                int f = tid + j * 256;
                int kk = f >> 6, cq = f & 63;
                cpasync16(&Ws[cur ^ 1][kk][cq * 4],
                          &g_WwihT[(k0n + kk) * 2048 + c0 + cq * 4]);
            }
            cpasync_commit();
        }
#pragma unroll
        for (int k = 0; k < 16; k++) {
            float4 b = *(float4*)&Ws[cur][k][tx * 4];
            unsigned long long bs0 = splat2(b.x);
            unsigned long long bs1 = splat2(b.y);
            unsigned long long bs2 = splat2(b.z);
            unsigned long long bs3 = splat2(b.w);
            ulonglong2 A0 = *(const ulonglong2*)&Xs[cur][k][ty * 16 + 0];
            ulonglong2 A1 = *(const ulonglong2*)&Xs[cur][k][ty * 16 + 4];
            ulonglong2 A2 = *(const ulonglong2*)&Xs[cur][k][ty * 16 + 8];
            ulonglong2 A3 = *(const ulonglong2*)&Xs[cur][k][ty * 16 + 12];
            unsigned long long ap[8] = {A0.x, A0.y, A1.x, A1.y, A2.x, A2.y, A3.x, A3.y};
#pragma unroll
            for (int rp = 0; rp < 8; rp++) {
                ffma2(acc2[rp][0], ap[rp], bs0);
                ffma2(acc2[rp][1], ap[rp], bs1);
                ffma2(acc2[rp][2], ap[rp], bs2);
                ffma2(acc2[rp][3], ap[rp], bs3);
            }
        }
        if (more) {
            Xs[cur ^ 1][xkq * 4 + 0][xtok] = xv.x;
            Xs[cur ^ 1][xkq * 4 + 1][xtok] = xv.y;
            Xs[cur ^ 1][xkq * 4 + 2][xtok] = xv.z;
            Xs[cur ^ 1][xkq * 4 + 3][xtok] = xv.w;
            cpasync_wait0();
            __syncthreads();
        }
    }

    float4 bias = *(const float4*)&g_bwp[c0 + tx * 4];
#pragma unroll
    for (int rp = 0; rp < 8; rp++) {
        float2 o0 = unpack2(acc2[rp][0]);
        float2 o1 = unpack2(acc2[rp][1]);
        float2 o2 = unpack2(acc2[rp][2]);
        float2 o3 = unpack2(acc2[rp][3]);
#pragma unroll
        for (int hh = 0; hh < 2; hh++) {
            int tok = tok0 + ty * 16 + rp * 2 + hh;
            float4 o;
            o.x = (hh ? o0.y : o0.x) + bias.x;
            o.y = (hh ? o1.y : o1.x) + bias.y;
            o.z = (hh ? o2.y : o2.x) + bias.z;
            o.w = (hh ? o3.y : o3.x) + bias.w;
            *(float4*)&g_XW[(size_t)tok * 2048 + c0 + tx * 4] = o;
        }
    }
}

// ---------------- word LSTM: subgrid decomposition + high-reuse dot (R12) ----------
#define WWS_STRIDE 68
#define WWS_FLOATS (512 * WWS_STRIDE)
#define WHS_STRIDE 516
#define WHS_FLOATS (8 * WHS_STRIDE)
#define WPS_FLOATS (8 * 32 * 20)
#define WORD_SMEM_BYTES ((WWS_FLOATS + WHS_FLOATS + WPS_FLOATS) * 4)
#define WORD_THREADS 256

__device__ __forceinline__ void word_fill_ws(float* ws, int c0, int tid)
{
    for (int idx = tid; idx < 512 * 64; idx += WORD_THREADS) {
        int k = idx >> 6, j = idx & 63;
        ws[k * WWS_STRIDE + j] = g_WwhhT[k * 2048 + c0 + j];
    }
}

__device__ __forceinline__ void word_fill_hs(float* hs, int t, int b0, int tid)
{
    if (t == 0) {
        for (int i = tid; i < WHS_FLOATS; i += WORD_THREADS) hs[i] = 0.f;
    } else {
#pragma unroll 4
        for (int i = tid; i < 1024; i += WORD_THREADS) {
            int bb = i >> 7, k4 = i & 127;
            float4 v = __ldcg((const float4*)&g_Hsave[
                (size_t)(((b0 + bb) << 10) + (t - 1)) * NH + k4 * 4]);
            *(float4*)&hs[bb * WHS_STRIDE + k4 * 4] = v;
        }
    }
}

__device__ __forceinline__ float word_step_body(float* ws, float* hs, float* ps,
                                                int t, int tid, int c0, int b0, float c)
{
    const int ks  = tid >> 5;
    const int pos = tid & 31;
    const int u_l = pos >> 1;
    const int bq  = pos & 1;
    const int k0  = ks * 64;

    word_fill_hs(hs, t, b0, tid);
    __syncthreads();

    float4 acc[4];
    acc[0] = make_float4(0.f, 0.f, 0.f, 0.f);
    acc[1] = make_float4(0.f, 0.f, 0.f, 0.f);
    acc[2] = make_float4(0.f, 0.f, 0.f, 0.f);
    acc[3] = make_float4(0.f, 0.f, 0.f, 0.f);

    const float* hbase = &hs[(bq * 4) * WHS_STRIDE];
#pragma unroll 4
    for (int k = k0; k < k0 + 64; k += 4) {
        float4 w0 = *(const float4*)&ws[(k + 0) * WWS_STRIDE + u_l * 4];
        float4 w1 = *(const float4*)&ws[(k + 1) * WWS_STRIDE + u_l * 4];
        float4 w2 = *(const float4*)&ws[(k + 2) * WWS_STRIDE + u_l * 4];
        float4 w3 = *(const float4*)&ws[(k + 3) * WWS_STRIDE + u_l * 4];
#pragma unroll
        for (int j = 0; j < 4; j++) {
            float4 hb = *(const float4*)&hbase[j * WHS_STRIDE + k];
            acc[j].x += hb.x * w0.x; acc[j].y += hb.x * w0.y;
            acc[j].z += hb.x * w0.z; acc[j].w += hb.x * w0.w;
            acc[j].x += hb.y * w1.x; acc[j].y += hb.y * w1.y;
            acc[j].z += hb.y * w1.z; acc[j].w += hb.y * w1.w;
            acc[j].x += hb.z * w2.x; acc[j].y += hb.z * w2.y;
            acc[j].z += hb.z * w2.z; acc[j].w += hb.z * w2.w;
            acc[j].x += hb.w * w3.x; acc[j].y += hb.w * w3.y;
            acc[j].z += hb.w * w3.z; acc[j].w += hb.w * w3.w;
        }
    }

    float* pp = &ps[(ks * 32 + pos) * 20];
    *(float4*)&pp[0]  = acc[0];
    *(float4*)&pp[4]  = acc[1];
    *(float4*)&pp[8]  = acc[2];
    *(float4*)&pp[12] = acc[3];
    __syncthreads();

    if (tid < 128) {
        const int pos2 = tid >> 2;
        const int j    = tid & 3;
        const int u_l2 = pos2 >> 1;
        const int bq2  = pos2 & 1;
        const int b    = bq2 * 4 + j;
        const int ug   = (c0 >> 2) + u_l2;

        float4 g = make_float4(0.f, 0.f, 0.f, 0.f);
#pragma unroll
        for (int s = 0; s < 8; s++) {
            float4 p = *(const float4*)&ps[(s * 32 + pos2) * 20 + j * 4];
            g.x += p.x; g.y += p.y; g.z += p.z; g.w += p.w;
        }
        const size_t n = (size_t)((b0 + b) << 10) + t;
        float4 a = *(const float4*)&g_XW[n * 2048 + c0 + u_l2 * 4];
        float gi = g.x + a.x;
        float gf = g.y + a.y;
        float gg = g.z + a.z;
        float go = g.w + a.w;
        c = sigm_(gf) * c + sigm_(gi) * tanh_(gg);
        float h = sigm_(go) * tanh_(c);
        __stcg(&g_Hsave[n * NH + ug], h);
    }
    return c;
}

__global__ __launch_bounds__(WORD_THREADS, 1)
void word_coop_kernel(int /*dummy*/)
{
    extern __shared__ float sm[];
    float* ws = sm;
    float* hs = sm + WWS_FLOATS;
    float* ps = hs + WHS_FLOATS;

    const int tid = threadIdx.x;
    const int sub = blockIdx.x >> 5;
    const int cg_ = blockIdx.x & 31;
    const int c0  = cg_ * 64;
    const int b0  = sub * 8;

    word_fill_ws(ws, c0, tid);

    float c = 0.f;
    for (int t = 0; t < NS; t++) {
        c = word_step_body(ws, hs, ps, t, tid, c0, b0, c);

        __threadfence();
        __syncthreads();
        if (tid == 0) {
            atomicAdd(&g_bar4[sub], 1u);
            const unsigned target = (unsigned)(t + 1) * 32u;
            while (*(volatile unsigned int*)&g_bar4[sub] < target) __nanosleep(32);
            __threadfence();
        }
        __syncthreads();
    }
}

__global__ __launch_bounds__(WORD_THREADS, 1)
void word_step_kernel(int t)
{
    extern __shared__ float sm[];
    float* ws = sm;
    float* hs = sm + WWS_FLOATS;
    float* ps = hs + WHS_FLOATS;

    const int tid = threadIdx.x;
    const int sub = blockIdx.x >> 5;
    const int cg_ = blockIdx.x & 31;
    const int c0  = cg_ * 64;
    const int b0  = sub * 8;

    word_fill_ws(ws, c0, tid);

    const int pos2 = tid >> 2;
    const int j    = tid & 3;
    const int u_l2 = pos2 >> 1;
    const int bq2  = pos2 & 1;
    const int b    = bq2 * 4 + j;
    const int ug   = (c0 >> 2) + u_l2;

    float c = 0.f;
    if (t > 0 && tid < 128) c = g_Cw[(b0 + b) * NH + ug];
    c = word_step_body(ws, hs, ps, t, tid, c0, b0, c);
    if (tid < 128) g_Cw[(b0 + b) * NH + ug] = c;
}

// ---------------- logits + log_softmax ----------------
__global__ __launch_bounds__(256, 1)
void logits_kernel(const float* __restrict__ Wt, const float* __restrict__ bt,
                   float* __restrict__ out)
{
    extern __shared__ float sm[];
    float* Wts = sm;               // [512][65]
    float* hs  = sm + 512 * 65;    // [4][512]
    __shared__ float sl[4][64];

    const int tid = threadIdx.x;
    for (int idx = tid; idx < 512 * 64; idx += 256) {
        int tg = idx >> 9, k = idx & 511;
        Wts[k * 65 + tg] = (tg < NT) ? Wt[tg * NH + k] : 0.f;
    }
    const int tokl = tid >> 6, tag = tid & 63;
    const int wid = tid >> 5, lane = tid & 31;
    float btv = (tag < NT) ? bt[tag] : 0.f;

    for (int tb = blockIdx.x; tb < NTOK / 4; tb += gridDim.x) {
        __syncthreads();
        for (int idx = tid; idx < 2048; idx += 256) {
            int tk = idx >> 9, k = idx & 511;
            hs[tk * 512 + k] = g_Hsave[(size_t)(tb * 4 + tk) * NH + k];
        }
        __syncthreads();
        float acc = 0.f;
#pragma unroll 8
        for (int k = 0; k < 512; k++)
            acc += hs[tokl * 512 + k] * Wts[k * 65 + tag];
        sl[tokl][tag] = (tag < NT) ? (acc + btv) : -1e30f;
        __syncthreads();
        if (wid < 4) {
            float l0 = sl[wid][lane], l1 = sl[wid][lane + 32];
            float m = fmaxf(l0, l1);
#pragma unroll
            for (int o = 16; o; o >>= 1) m = fmaxf(m, __shfl_xor_sync(0xffffffffu, m, o));
            float s = __expf(l0 - m) + __expf(l1 - m);
#pragma unroll
            for (int o = 16; o; o >>= 1) s += __shfl_xor_sync(0xffffffffu, s, o);
            float lse = m + __logf(s);
            int n = tb * 4 + wid;
            for (int j = lane; j < NT; j += 32)
                out[(size_t)n * NT + j] = sl[wid][j] - lse;
        }
    }
}

// ---------------- launch ----------------
extern "C" void kernel_launch(void* const* d_in, const int* in_sizes, int n_in,
                              void* d_out, int out_size)
{
    const int*   char_idx = (const int*)d_in[0];
    const int*   word_idx = (const int*)d_in[1];
    const float* char_emb = (const float*)d_in[2];
    const float* word_emb = (const float*)d_in[3];
    const float* Wc_ih    = (const float*)d_in[4];
    const float* Wc_hh    = (const float*)d_in[5];
    const float* bc       = (const float*)d_in[6];
    const float* Ww_ih    = (const float*)d_in[7];
    const float* Ww_hh    = (const float*)d_in[8];
    const float* bw       = (const float*)d_in[9];
    const float* Wt       = (const float*)d_in[10];
    const float* bt       = (const float*)d_in[11];
    float* out = (float*)d_out;

    const int word_smem   = WORD_SMEM_BYTES;             // 176256 B
    const int logits_smem = (512 * 65 + 4 * 512) * 4;    // 141312 B
    cudaFuncSetAttribute(word_coop_kernel,
                         cudaFuncAttributeMaxDynamicSharedMemorySize, word_smem);
    cudaFuncSetAttribute(word_step_kernel,
                         cudaFuncAttributeMaxDynamicSharedMemorySize, word_smem);
    cudaFuncSetAttribute(logits_kernel,
                         cudaFuncAttributeMaxDynamicSharedMemorySize, logits_smem);

    // Deterministic host-side decision: cooperative path only if the device
    // guarantees 128 co-resident CTAs (pure queries, capture-legal).
    int dev = 0;
    cudaGetDevice(&dev);
    int numSM = 0, coopAttr = 0, perSM = 0;
    cudaDeviceGetAttribute(&numSM, cudaDevAttrMultiProcessorCount, dev);
    cudaDeviceGetAttribute(&coopAttr, cudaDevAttrCooperativeLaunch, dev);
    cudaOccupancyMaxActiveBlocksPerMultiprocessor(&perSM, word_coop_kernel,
                                                  WORD_THREADS, word_smem);
    const bool coop_ok = (coopAttr != 0) && (perSM >= 1) && (numSM >= 128);

    prep_all_kernel<<<4096, 256>>>(Wc_ih, Wc_hh, bc, Ww_ih, Ww_hh, bw);

    eih_kernel<<<NCS, 256>>>(char_emb);

    char_init_kernel<<<NTOK * NE / 256, 256>>>(char_idx);

    for (int t = 1; t < NC; t++)
        char_step_kernel<<<dim3(NTOK / 64, 4), 256>>>(char_idx, t);

    xw_kernel<<<dim3(NTOK / 64, 8), 256>>>(word_idx, word_emb);

    if (coop_ok) {
        int dummy = 0;
        void* kargs[] = { &dummy };
        cudaLaunchCooperativeKernel((void*)word_coop_kernel,
                                    dim3(128), dim3(WORD_THREADS),
                                    kargs, (size_t)word_smem, (cudaStream_t)0);
    } else {
        for (int t = 0; t < NS; t++)
            word_step_kernel<<<128, WORD_THREADS, word_smem>>>(t);
    }

    logits_kernel<<<148, 256, logits_smem>>>(Wt, bt, out);
}